// round 9
// baseline (speedup 1.0000x reference)
#include <cuda_runtime.h>
#include <cuda_bf16.h>
#include <cstdint>

#define LN_EPS 1e-5f

// ---------------- scratch (device globals: allocation-free) ----------------
__device__ __align__(128) float g_y0[100000 * 128];
__device__ __align__(128) float g_y1[100000 * 256];
__device__ __align__(128) float g_y2[100000 * 512];
__device__ __align__(128) __nv_bfloat16 g_w1thi0[64*64],  g_w1tlo0[64*64];
__device__ __align__(128) __nv_bfloat16 g_w1thi1[64*128], g_w1tlo1[64*128];
__device__ __align__(128) __nv_bfloat16 g_w1thi2[64*256], g_w1tlo2[64*256];
__device__ __align__(128) __nv_bfloat16 g_w2thi0[64*64],  g_w2tlo0[64*64];
__device__ __align__(128) __nv_bfloat16 g_w2thi1[128*64], g_w2tlo1[128*64];
__device__ __align__(128) __nv_bfloat16 g_w2thi2[256*64], g_w2tlo2[256*64];
__device__ float g_colsq[512];

// CSR scratch
__device__ int g_deg[100000];
__device__ int g_rowptr[100000];
__device__ int g_cursor[100000];
__device__ int g_esrc[800000];
__device__ int g_cdeg[10000];
__device__ int g_cptr[10000];
__device__ int g_ccur[10000];
__device__ int g_cnodes[100000];
__device__ int g_bsumsN[512];
__device__ int g_bsumsC[512];

__device__ __forceinline__ float neg_inf() { return __int_as_float(0xff800000); }

__device__ __forceinline__ void split2(float a, float b, uint32_t& hi, uint32_t& lo) {
    __nv_bfloat16 ah = __float2bfloat16_rn(a);
    __nv_bfloat16 bh = __float2bfloat16_rn(b);
    __nv_bfloat16 al = __float2bfloat16_rn(a - __bfloat162float(ah));
    __nv_bfloat16 bl = __float2bfloat16_rn(b - __bfloat162float(bh));
    __nv_bfloat162 h = __halves2bfloat162(ah, bh);
    __nv_bfloat162 l = __halves2bfloat162(al, bl);
    hi = *reinterpret_cast<uint32_t*>(&h);
    lo = *reinterpret_cast<uint32_t*>(&l);
}

__device__ __forceinline__ void mma16816(float* c, const uint32_t* a,
                                         uint32_t b0, uint32_t b1) {
    asm volatile(
        "mma.sync.aligned.m16n8k16.row.col.f32.bf16.bf16.f32 "
        "{%0,%1,%2,%3}, {%4,%5,%6,%7}, {%8,%9}, {%0,%1,%2,%3};"
        : "+f"(c[0]), "+f"(c[1]), "+f"(c[2]), "+f"(c[3])
        : "r"(a[0]), "r"(a[1]), "r"(a[2]), "r"(a[3]), "r"(b0), "r"(b1));
}

__device__ __forceinline__ uint32_t sm_off(const void* p) {
    uint32_t a;
    asm("{ .reg .u64 t; cvta.to.shared.u64 t, %1; cvt.u32.u64 %0, t; }" : "=r"(a) : "l"(p));
    return a;
}

__device__ __forceinline__ void ldsm_x4(uint32_t& r0, uint32_t& r1,
                                        uint32_t& r2, uint32_t& r3, uint32_t addr) {
    asm volatile("ldmatrix.sync.aligned.m8n8.x4.shared.b16 {%0,%1,%2,%3}, [%4];"
                 : "=r"(r0), "=r"(r1), "=r"(r2), "=r"(r3) : "r"(addr));
}

// ---------------- init: zero CSR counters + convert all weights -------------
struct WConv {
    const float* in[6];
    __nv_bfloat16* hi[6];
    __nv_bfloat16* lo[6];
    int K[6], M[6];
    int off[7];
};

__global__ void init_misc(WConv a, int* __restrict__ deg, int* __restrict__ cursor,
                          int* __restrict__ cdeg, int* __restrict__ ccur,
                          float* __restrict__ colsq, int n, int nc)
{
    int gid = blockIdx.x * blockDim.x + threadIdx.x;
    if (gid < n) { deg[gid] = 0; cursor[gid] = 0; }
    if (gid < nc) { cdeg[gid] = 0; ccur[gid] = 0; }
    if (gid < 512) colsq[gid] = 0.f;
    if (gid < a.off[6]) {
        int s = 0;
#pragma unroll
        for (int i = 1; i < 6; i++) if (gid >= a.off[i]) s = i;
        int local = gid - a.off[s];
        int M = a.M[s], K = a.K[s];
        int k = local / M, m = local - k * M;
        float v = __ldg(a.in[s] + local);
        __nv_bfloat16 h = __float2bfloat16_rn(v);
        a.hi[s][m * K + k] = h;
        a.lo[s][m * K + k] = __float2bfloat16_rn(v - __bfloat162float(h));
    }
}

// ---------------- CSR build --------------------------------------------------
__global__ void hist_fused(const int* __restrict__ ei, int E,
                           const int* __restrict__ cluster, int n,
                           int* __restrict__ deg, int* __restrict__ cdeg)
{
    int gid = blockIdx.x * blockDim.x + threadIdx.x;
    if (gid < E) {
        atomicAdd(&deg[__ldg(ei + E + gid)], 1);
    } else if (gid < E + n) {
        atomicAdd(&cdeg[__ldg(cluster + gid - E)], 1);
    }
}

__global__ __launch_bounds__(512) void scan_block2(
    const int* __restrict__ inN, int* __restrict__ outN, int* __restrict__ sumsN, int n, int nbN,
    const int* __restrict__ inC, int* __restrict__ outC, int* __restrict__ sumsC, int nc)
{
    __shared__ int s[512];
    int tid = threadIdx.x;
    const int* in;  int* out; int* sums; int len; int blk;
    if ((int)blockIdx.x < nbN) { in = inN; out = outN; sums = sumsN; len = n;  blk = blockIdx.x; }
    else                       { in = inC; out = outC; sums = sumsC; len = nc; blk = blockIdx.x - nbN; }
    int i = blk * 512 + tid;
    int v = (i < len) ? in[i] : 0;
    s[tid] = v;
    __syncthreads();
#pragma unroll
    for (int off = 1; off < 512; off <<= 1) {
        int t = (tid >= off) ? s[tid - off] : 0;
        __syncthreads();
        s[tid] += t;
        __syncthreads();
    }
    if (i < len) out[i] = s[tid] - v;
    if (tid == 511) sums[blk] = s[511];
}

__global__ __launch_bounds__(512) void scan_add_fused(
    int* __restrict__ outN, const int* __restrict__ sumsN, int n, int nbN,
    int* __restrict__ outC, const int* __restrict__ sumsC, int nc)
{
    __shared__ int red[16];
    __shared__ int total;
    int tid = threadIdx.x;
    int* out; const int* sums; int len; int blk;
    if ((int)blockIdx.x < nbN) { out = outN; sums = sumsN; len = n;  blk = blockIdx.x; }
    else                       { out = outC; sums = sumsC; len = nc; blk = blockIdx.x - nbN; }
    int p = 0;
    for (int i = tid; i < blk; i += 512) p += sums[i];
#pragma unroll
    for (int off = 16; off >= 1; off >>= 1) p += __shfl_xor_sync(0xffffffffu, p, off);
    if ((tid & 31) == 0) red[tid >> 5] = p;
    __syncthreads();
    if (tid == 0) {
        int t = 0;
#pragma unroll
        for (int i = 0; i < 16; i++) t += red[i];
        total = t;
    }
    __syncthreads();
    int i = blk * 512 + tid;
    if (i < len) out[i] += total;
}

__global__ void scatter_fused(const int* __restrict__ ei, int E,
                              const int* __restrict__ cluster, int n,
                              const int* __restrict__ rowptr, int* __restrict__ cursor,
                              int* __restrict__ esrc,
                              const int* __restrict__ cptr, int* __restrict__ ccur,
                              int* __restrict__ cnodes)
{
    int gid = blockIdx.x * blockDim.x + threadIdx.x;
    if (gid < E) {
        int src = __ldg(ei + gid);
        int tgt = __ldg(ei + E + gid);
        int pos = rowptr[tgt] + atomicAdd(&cursor[tgt], 1);
        esrc[pos] = src;
    } else if (gid < E + n) {
        int i = gid - E;
        int cl = __ldg(cluster + i);
        int pos = cptr[cl] + atomicAdd(&ccur[cl], 1);
        cnodes[pos] = i;
    }
}

// ---------------- fused MLP layer (W1/W2 smem overlay) ----------------------
// Ain [n, C] fp32; W1T [64][C] split bf16, W2T [C][64] split bf16
// Y [n, 2C] fp32: first C cols written here, rest by agg
template<int C>
__global__ __launch_bounds__(256) void fused_mlp(
    const float* __restrict__ Ain,
    const __nv_bfloat16* __restrict__ W1hi, const __nv_bfloat16* __restrict__ W1lo,
    const float* __restrict__ b1, const float* __restrict__ gam,
    const float* __restrict__ bet,
    const __nv_bfloat16* __restrict__ W2hi, const __nv_bfloat16* __restrict__ W2lo,
    const float* __restrict__ b2,
    float* __restrict__ Y, int n)
{
    constexpr int AS   = 72;
    constexpr int WS   = C + 8;
    constexpr int NKC  = C / 64;
    constexpr int NG   = C / 64;
    constexpr int AE   = 128 * AS;
    constexpr int W1E  = 64 * WS;
    constexpr int W2E  = C * AS;
    constexpr int WMAX = (W1E > W2E) ? W1E : W2E;
    extern __shared__ __align__(16) __nv_bfloat16 sm[];
    __nv_bfloat16* Ws0 = sm;                 // W1 then W2 (overlay)
    __nv_bfloat16* Ws1 = sm + WMAX;
    __nv_bfloat16* As0 = sm + 2 * WMAX;      // A then H
    __nv_bfloat16* As1 = As0 + AE;

    const int tid = threadIdx.x, wid = tid >> 5, lane = tid & 31;
    const int g = lane >> 2, q = lane & 3;
    const int r0b = blockIdx.x * 128;

    // load W1 [64][C] split
    {
        constexpr int VPR = C / 8;
        for (int i = tid; i < 64 * VPR; i += 256) {
            int m = i / VPR, seg = i - m * VPR;
            *(uint4*)&Ws0[m * WS + seg * 8] = __ldg((const uint4*)(W1hi + (size_t)m * C) + seg);
            *(uint4*)&Ws1[m * WS + seg * 8] = __ldg((const uint4*)(W1lo + (size_t)m * C) + seg);
        }
    }

    // per-thread ldmatrix address bases
    const int arow = wid * 16 + (lane & 15);
    const int acol = ((lane >> 4) & 1) * 8;
    const uint32_t a_hi = sm_off(As0 + arow * AS + acol);
    const uint32_t a_lo = sm_off(As1 + arow * AS + acol);
    const int brow = (lane & 7) + ((lane >> 4) << 3);
    const int bk8  = ((lane >> 3) & 1) * 8;
    const uint32_t w1h_b = sm_off(Ws0 + brow * WS + bk8);
    const uint32_t w1l_b = sm_off(Ws1 + brow * WS + bk8);
    const uint32_t w2h_b = sm_off(Ws0 + brow * AS + bk8);
    const uint32_t w2l_b = sm_off(Ws1 + brow * AS + bk8);

    float acc[8][4] = {};

    for (int kc = 0; kc < NKC; kc++) {
        __syncthreads();
        for (int i = tid; i < 128 * 32; i += 256) {
            int m = i >> 5, e = i & 31;
            int r = r0b + m;
            uint32_t h = 0, l = 0;
            if (r < n) {
                float2 v = __ldg((const float2*)Ain + (size_t)r * (C / 2) + kc * 32 + e);
                split2(v.x, v.y, h, l);
            }
            *(uint32_t*)&As0[m * AS + 2 * e] = h;
            *(uint32_t*)&As1[m * AS + 2 * e] = l;
        }
        __syncthreads();

#pragma unroll
        for (int ks = 0; ks < 4; ks++) {
            const int k0 = ks * 16;
            uint32_t ah[4], al[4];
            ldsm_x4(ah[0], ah[1], ah[2], ah[3], a_hi + k0 * 2);
            ldsm_x4(al[0], al[1], al[2], al[3], a_lo + k0 * 2);
            const int kg = kc * 64 + k0;
#pragma unroll
            for (int jj = 0; jj < 8; jj += 2) {
                uint32_t p0, p1, p2, p3, l0, l1, l2, l3;
                ldsm_x4(p0, p1, p2, p3, w1h_b + (8 * jj * WS + kg) * 2);
                ldsm_x4(l0, l1, l2, l3, w1l_b + (8 * jj * WS + kg) * 2);
                mma16816(acc[jj],     ah, p0, p1);
                mma16816(acc[jj],     ah, l0, l1);
                mma16816(acc[jj],     al, p0, p1);
                mma16816(acc[jj + 1], ah, p2, p3);
                mma16816(acc[jj + 1], ah, l2, l3);
                mma16816(acc[jj + 1], al, p2, p3);
            }
        }
    }

    // ---- gemm1 epilogue: bias + LN (quad shuffle) + ReLU -> H in As --------
    {
        float v0[16], v1[16];
        float s0 = 0.f, q0 = 0.f, s1 = 0.f, q1 = 0.f;
#pragma unroll
        for (int j = 0; j < 8; j++) {
            int c0 = 8*j + 2*q;
            float bx = __ldg(b1 + c0), by = __ldg(b1 + c0 + 1);
            float a = acc[j][0] + bx, b = acc[j][1] + by;
            float c = acc[j][2] + bx, d = acc[j][3] + by;
            v0[2*j] = a; v0[2*j+1] = b; v1[2*j] = c; v1[2*j+1] = d;
            s0 += a + b; q0 += a*a + b*b;
            s1 += c + d; q1 += c*c + d*d;
        }
#pragma unroll
        for (int off = 1; off < 4; off <<= 1) {
            s0 += __shfl_xor_sync(0xffffffffu, s0, off);
            q0 += __shfl_xor_sync(0xffffffffu, q0, off);
            s1 += __shfl_xor_sync(0xffffffffu, s1, off);
            q1 += __shfl_xor_sync(0xffffffffu, q1, off);
        }
        float mu0 = s0 * (1.f/64.f), var0 = q0 * (1.f/64.f) - mu0*mu0;
        float mu1 = s1 * (1.f/64.f), var1 = q1 * (1.f/64.f) - mu1*mu1;
        float rs0 = rsqrtf(var0 + LN_EPS), rs1 = rsqrtf(var1 + LN_EPS);
        __syncthreads();          // all gemm1 MMA reads of As/Ws done
        int rl0 = wid * 16 + g, rl1 = rl0 + 8;
#pragma unroll
        for (int j = 0; j < 8; j++) {
            int c0 = 8*j + 2*q;
            float ga = __ldg(gam + c0), gb = __ldg(gam + c0 + 1);
            float ba = __ldg(bet + c0), bb = __ldg(bet + c0 + 1);
            float f0 = fmaxf((v0[2*j]   - mu0) * rs0 * ga + ba, 0.f);
            float f1 = fmaxf((v0[2*j+1] - mu0) * rs0 * gb + bb, 0.f);
            float f2 = fmaxf((v1[2*j]   - mu1) * rs1 * ga + ba, 0.f);
            float f3 = fmaxf((v1[2*j+1] - mu1) * rs1 * gb + bb, 0.f);
            uint32_t h, l;
            split2(f0, f1, h, l);
            *(uint32_t*)&As0[rl0 * AS + c0] = h;
            *(uint32_t*)&As1[rl0 * AS + c0] = l;
            split2(f2, f3, h, l);
            *(uint32_t*)&As0[rl1 * AS + c0] = h;
            *(uint32_t*)&As1[rl1 * AS + c0] = l;
        }
    }
    // ---- load W2 [C][64] split into overlaid W region ----------------------
    for (int i = tid; i < C * 8; i += 256) {
        int m = i >> 3, seg = i & 7;
        *(uint4*)&Ws0[m * AS + seg * 8] = __ldg((const uint4*)(W2hi + (size_t)m * 64) + seg);
        *(uint4*)&Ws1[m * AS + seg * 8] = __ldg((const uint4*)(W2lo + (size_t)m * 64) + seg);
    }
    __syncthreads();

    // ---- gemm2: H[128,64] @ W2 -> Y[:, 0:C] --------------------------------
    const int rg0 = r0b + wid * 16 + g;
    const int rg1 = rg0 + 8;

#pragma unroll
    for (int ng = 0; ng < NG; ng++) {
        float acc2[8][4] = {};
#pragma unroll
        for (int ks = 0; ks < 4; ks++) {
            const int k0 = ks * 16;
            uint32_t ah[4], al[4];
            ldsm_x4(ah[0], ah[1], ah[2], ah[3], a_hi + k0 * 2);
            ldsm_x4(al[0], al[1], al[2], al[3], a_lo + k0 * 2);
#pragma unroll
            for (int jj = 0; jj < 8; jj += 2) {
                uint32_t p0, p1, p2, p3, l0, l1, l2, l3;
                ldsm_x4(p0, p1, p2, p3, w2h_b + ((ng * 64 + 8 * jj) * AS + k0) * 2);
                ldsm_x4(l0, l1, l2, l3, w2l_b + ((ng * 64 + 8 * jj) * AS + k0) * 2);
                mma16816(acc2[jj],     ah, p0, p1);
                mma16816(acc2[jj],     ah, l0, l1);
                mma16816(acc2[jj],     al, p0, p1);
                mma16816(acc2[jj + 1], ah, p2, p3);
                mma16816(acc2[jj + 1], ah, l2, l3);
                mma16816(acc2[jj + 1], al, p2, p3);
            }
        }
        if (rg0 < n) {
            float2* orow = (float2*)(Y + (size_t)rg0 * (2 * C)) + ng * 32;
#pragma unroll
            for (int j = 0; j < 8; j++) {
                int c0 = 8*j + 2*q;
                orow[4*j + q] = make_float2(acc2[j][0] + __ldg(b2 + ng*64 + c0),
                                            acc2[j][1] + __ldg(b2 + ng*64 + c0 + 1));
            }
        }
        if (rg1 < n) {
            float2* orow = (float2*)(Y + (size_t)rg1 * (2 * C)) + ng * 32;
#pragma unroll
            for (int j = 0; j < 8; j++) {
                int c0 = 8*j + 2*q;
                orow[4*j + q] = make_float2(acc2[j][2] + __ldg(b2 + ng*64 + c0),
                                            acc2[j][3] + __ldg(b2 + ng*64 + c0 + 1));
            }
        }
    }
}

// ---------------- CSR gather-max aggregation (fp32, unrolled x4) ------------
template<int C>
__global__ __launch_bounds__(256) void agg_f(
    float* __restrict__ Y, const int* __restrict__ rowptr,
    const int* __restrict__ deg, const int* __restrict__ esrc, int n)
{
    int w = (blockIdx.x * blockDim.x + threadIdx.x) >> 5;
    if (w >= n) return;
    const int lane = threadIdx.x & 31;
    constexpr int EPL = C / 64;              // float2 entries per lane
    float2 mx[EPL];
#pragma unroll
    for (int i = 0; i < EPL; i++) mx[i] = make_float2(neg_inf(), neg_inf());
    int d = __ldg(deg + w), base = __ldg(rowptr + w);
    int j = 0;
    for (; j + 3 < d; j += 4) {
        int s0 = __ldg(esrc + base + j);
        int s1 = __ldg(esrc + base + j + 1);
        int s2 = __ldg(esrc + base + j + 2);
        int s3 = __ldg(esrc + base + j + 3);
        const float2* r0 = (const float2*)(Y + (size_t)s0 * (2 * C));
        const float2* r1 = (const float2*)(Y + (size_t)s1 * (2 * C));
        const float2* r2 = (const float2*)(Y + (size_t)s2 * (2 * C));
        const float2* r3 = (const float2*)(Y + (size_t)s3 * (2 * C));
#pragma unroll
        for (int i = 0; i < EPL; i++) {
            float2 v0 = __ldg(r0 + lane + i * 32);
            float2 v1 = __ldg(r1 + lane + i * 32);
            float2 v2 = __ldg(r2 + lane + i * 32);
            float2 v3 = __ldg(r3 + lane + i * 32);
            float ax = fmaxf(fmaxf(v0.x, v1.x), fmaxf(v2.x, v3.x));
            float ay = fmaxf(fmaxf(v0.y, v1.y), fmaxf(v2.y, v3.y));
            mx[i].x = fmaxf(mx[i].x, ax);
            mx[i].y = fmaxf(mx[i].y, ay);
        }
    }
    for (; j < d; j++) {
        int s0 = __ldg(esrc + base + j);
        const float2* r0 = (const float2*)(Y + (size_t)s0 * (2 * C));
#pragma unroll
        for (int i = 0; i < EPL; i++) {
            float2 v0 = __ldg(r0 + lane + i * 32);
            mx[i].x = fmaxf(mx[i].x, v0.x);
            mx[i].y = fmaxf(mx[i].y, v0.y);
        }
    }
    float2* orow = (float2*)(Y + (size_t)w * (2 * C) + C);
#pragma unroll
    for (int i = 0; i < EPL; i++)
        orow[lane + i * 32] = d ? mx[i] : make_float2(0.f, 0.f);
}

// ---------------- cluster max-pool + fused column sum-of-squares ------------
__global__ __launch_bounds__(128) void pool_f(
    const float* __restrict__ Y, const int* __restrict__ cptr,
    const int* __restrict__ cdeg, const int* __restrict__ cnodes,
    float* __restrict__ out, float* __restrict__ colsq)
{
    int cl = blockIdx.x, t = threadIdx.x;
    int d = __ldg(cdeg + cl), base = __ldg(cptr + cl);
    float2 m0 = make_float2(neg_inf(), neg_inf());
    float2 m1 = m0;
    int j = 0;
    for (; j + 1 < d; j += 2) {
        int n0 = __ldg(cnodes + base + j);
        int n1 = __ldg(cnodes + base + j + 1);
        const float2* ra = (const float2*)(Y + (size_t)n0 * 512);
        const float2* rb = (const float2*)(Y + (size_t)n1 * 512);
        float2 a0 = __ldg(ra + t), a1 = __ldg(ra + t + 128);
        float2 b0 = __ldg(rb + t), b1 = __ldg(rb + t + 128);
        m0.x = fmaxf(m0.x, fmaxf(a0.x, b0.x)); m0.y = fmaxf(m0.y, fmaxf(a0.y, b0.y));
        m1.x = fmaxf(m1.x, fmaxf(a1.x, b1.x)); m1.y = fmaxf(m1.y, fmaxf(a1.y, b1.y));
    }
    if (j < d) {
        int n0 = __ldg(cnodes + base + j);
        const float2* ra = (const float2*)(Y + (size_t)n0 * 512);
        float2 a0 = __ldg(ra + t), a1 = __ldg(ra + t + 128);
        m0.x = fmaxf(m0.x, a0.x); m0.y = fmaxf(m0.y, a0.y);
        m1.x = fmaxf(m1.x, a1.x); m1.y = fmaxf(m1.y, a1.y);
    }
    if (!d) { m0 = make_float2(0.f, 0.f); m1 = m0; }
    float2* orow = (float2*)(out + (size_t)cl * 512);
    orow[t] = m0;
    orow[t + 128] = m1;
    atomicAdd(colsq + 2 * t,           m0.x * m0.x);
    atomicAdd(colsq + 2 * t + 1,       m0.y * m0.y);
    atomicAdd(colsq + 256 + 2 * t,     m1.x * m1.x);
    atomicAdd(colsq + 256 + 2 * t + 1, m1.y * m1.y);
}

__global__ void scale_kernel(float* __restrict__ out, const float* __restrict__ colsq, int nc)
{
    int gid = blockIdx.x * blockDim.x + threadIdx.x;
    if (gid >= nc * 512) return;
    int c = gid & 511;
    out[gid] = out[gid] * rsqrtf(__ldg(colsq + c));
}

// ---------------- launch ----------------------------------------------------
extern "C" void kernel_launch(void* const* d_in, const int* in_sizes, int n_in,
                              void* d_out, int out_size)
{
    const float* x       = (const float*)d_in[0];
    const int*   ei      = (const int*)d_in[1];
    const int*   cluster = (const int*)d_in[2];
    const int N  = in_sizes[0] / 64;
    const int E  = in_sizes[1] / 2;
    const int NC = out_size / 512;
    float* out = (float*)d_out;

    float *y0, *y1, *y2, *colsq;
    __nv_bfloat16 *w1h[3], *w1l[3], *w2h[3], *w2l[3];
    int *deg, *rowptr, *cursor, *esrc, *cdeg, *cptr, *ccur, *cnodes, *bsumsN, *bsumsC;
    cudaGetSymbolAddress((void**)&y0, g_y0);
    cudaGetSymbolAddress((void**)&y1, g_y1);
    cudaGetSymbolAddress((void**)&y2, g_y2);
    cudaGetSymbolAddress((void**)&w1h[0], g_w1thi0); cudaGetSymbolAddress((void**)&w1l[0], g_w1tlo0);
    cudaGetSymbolAddress((void**)&w1h[1], g_w1thi1); cudaGetSymbolAddress((void**)&w1l[1], g_w1tlo1);
    cudaGetSymbolAddress((void**)&w1h[2], g_w1thi2); cudaGetSymbolAddress((void**)&w1l[2], g_w1tlo2);
    cudaGetSymbolAddress((void**)&w2h[0], g_w2thi0); cudaGetSymbolAddress((void**)&w2l[0], g_w2tlo0);
    cudaGetSymbolAddress((void**)&w2h[1], g_w2thi1); cudaGetSymbolAddress((void**)&w2l[1], g_w2tlo1);
    cudaGetSymbolAddress((void**)&w2h[2], g_w2thi2); cudaGetSymbolAddress((void**)&w2l[2], g_w2tlo2);
    cudaGetSymbolAddress((void**)&colsq,  g_colsq);
    cudaGetSymbolAddress((void**)&deg,    g_deg);
    cudaGetSymbolAddress((void**)&rowptr, g_rowptr);
    cudaGetSymbolAddress((void**)&cursor, g_cursor);
    cudaGetSymbolAddress((void**)&esrc,   g_esrc);
    cudaGetSymbolAddress((void**)&cdeg,   g_cdeg);
    cudaGetSymbolAddress((void**)&cptr,   g_cptr);
    cudaGetSymbolAddress((void**)&ccur,   g_ccur);
    cudaGetSymbolAddress((void**)&cnodes, g_cnodes);
    cudaGetSymbolAddress((void**)&bsumsN, g_bsumsN);
    cudaGetSymbolAddress((void**)&bsumsC, g_bsumsC);

    // smem: 2*(2*WMAX + 2*128*72) bytes, WMAX = max(64*(C+8), C*72) elems
    const int SM64  = (2 * 4608  + 2 * 9216) * 2;   //  55296 -> 4 blocks/SM
    const int SM128 = (2 * 9216  + 2 * 9216) * 2;   //  73728 -> 3 blocks/SM
    const int SM256 = (2 * 18432 + 2 * 9216) * 2;   // 110592 -> 2 blocks/SM
    cudaFuncSetAttribute((const void*)fused_mlp<64>,  cudaFuncAttributeMaxDynamicSharedMemorySize, SM64);
    cudaFuncSetAttribute((const void*)fused_mlp<128>, cudaFuncAttributeMaxDynamicSharedMemorySize, SM128);
    cudaFuncSetAttribute((const void*)fused_mlp<256>, cudaFuncAttributeMaxDynamicSharedMemorySize, SM256);

    const int GRID = (N + 127) / 128;
    const int nbN = (N + 511) / 512;
    const int nbC = (NC + 511) / 512;

    // ---- init: zero counters + weight conversion (1 launch) ----
    {
        WConv a;
        int off = 0;
        const int CINs[3] = {64, 128, 256};
        for (int i = 0; i < 3; i++) {
            int c = CINs[i];
            a.in[2*i]   = (const float*)d_in[3 + 6*i];       // W1 [c][64] -> [64][c]
            a.hi[2*i]   = w1h[i]; a.lo[2*i] = w1l[i];
            a.K[2*i]    = c;  a.M[2*i] = 64;
            a.off[2*i]  = off; off += c * 64;
            a.in[2*i+1] = (const float*)d_in[3 + 6*i + 4];   // W2 [64][c] -> [c][64]
            a.hi[2*i+1] = w2h[i]; a.lo[2*i+1] = w2l[i];
            a.K[2*i+1]  = 64; a.M[2*i+1] = c;
            a.off[2*i+1] = off; off += 64 * c;
        }
        a.off[6] = off;
        int span = N > off ? N : off;
        init_misc<<<(span + 255) / 256, 256>>>(a, deg, cursor, cdeg, ccur, colsq, N, NC);
    }

    // ---- CSR build (4 launches) ----
    hist_fused<<<(E + N + 255) / 256, 256>>>(ei, E, cluster, N, deg, cdeg);
    scan_block2<<<nbN + nbC, 512>>>(deg, rowptr, bsumsN, N, nbN, cdeg, cptr, bsumsC, NC);
    scan_add_fused<<<nbN + nbC, 512>>>(rowptr, bsumsN, N, nbN, cptr, bsumsC, NC);
    scatter_fused<<<(E + N + 255) / 256, 256>>>(ei, E, cluster, N, rowptr, cursor, esrc,
                                                cptr, ccur, cnodes);

    // ---- layers ----
    fused_mlp<64><<<GRID, 256, SM64>>>(
        x, w1h[0], w1l[0], (const float*)d_in[4], (const float*)d_in[5],
        (const float*)d_in[6], w2h[0], w2l[0], (const float*)d_in[8], y0, N);
    agg_f<64><<<(N + 7) / 8, 256>>>(y0, rowptr, deg, esrc, N);

    fused_mlp<128><<<GRID, 256, SM128>>>(
        y0, w1h[1], w1l[1], (const float*)d_in[10], (const float*)d_in[11],
        (const float*)d_in[12], w2h[1], w2l[1], (const float*)d_in[14], y1, N);
    agg_f<128><<<(N + 7) / 8, 256>>>(y1, rowptr, deg, esrc, N);

    fused_mlp<256><<<GRID, 256, SM256>>>(
        y1, w1h[2], w1l[2], (const float*)d_in[16], (const float*)d_in[17],
        (const float*)d_in[18], w2h[2], w2l[2], (const float*)d_in[20], y2, N);
    agg_f<256><<<(N + 7) / 8, 256>>>(y2, rowptr, deg, esrc, N);

    // ---- cluster max-pool (+colsq) + column L2 normalize ----
    pool_f<<<NC, 128>>>(y2, cptr, cdeg, cnodes, out, colsq);
    scale_kernel<<<(NC * 512 + 255) / 256, 256>>>(out, colsq, NC);
}

// round 10
// speedup vs baseline: 1.2483x; 1.2483x over previous
#include <cuda_runtime.h>
#include <cuda_bf16.h>
#include <cstdint>

#define LN_EPS 1e-5f

// ---------------- scratch (device globals: allocation-free) ----------------
__device__ __align__(128) float g_y0[100000 * 128];
__device__ __align__(128) float g_y1[100000 * 256];
__device__ __align__(128) float g_y2[100000 * 512];
__device__ __align__(128) __nv_bfloat16 g_w1thi0[64*64],  g_w1tlo0[64*64];
__device__ __align__(128) __nv_bfloat16 g_w1thi1[64*128], g_w1tlo1[64*128];
__device__ __align__(128) __nv_bfloat16 g_w1thi2[64*256], g_w1tlo2[64*256];
__device__ __align__(128) __nv_bfloat16 g_w2thi0[64*64],  g_w2tlo0[64*64];
__device__ __align__(128) __nv_bfloat16 g_w2thi1[128*64], g_w2tlo1[128*64];
__device__ __align__(128) __nv_bfloat16 g_w2thi2[256*64], g_w2tlo2[256*64];
__device__ float g_colsq[512];

// CSR scratch
__device__ int g_deg[100000];
__device__ int g_rowptr[100000];
__device__ int g_cursor[100000];
__device__ int g_esrc[800000];
__device__ int g_cdeg[10000];
__device__ int g_cptr[10000];
__device__ int g_ccur[10000];
__device__ int g_cnodes[100000];
__device__ int g_bsumsN[512];
__device__ int g_bsumsC[512];

__device__ __forceinline__ float neg_inf() { return __int_as_float(0xff800000); }

__device__ __forceinline__ void split2(float a, float b, uint32_t& hi, uint32_t& lo) {
    __nv_bfloat16 ah = __float2bfloat16_rn(a);
    __nv_bfloat16 bh = __float2bfloat16_rn(b);
    __nv_bfloat16 al = __float2bfloat16_rn(a - __bfloat162float(ah));
    __nv_bfloat16 bl = __float2bfloat16_rn(b - __bfloat162float(bh));
    __nv_bfloat162 h = __halves2bfloat162(ah, bh);
    __nv_bfloat162 l = __halves2bfloat162(al, bl);
    hi = *reinterpret_cast<uint32_t*>(&h);
    lo = *reinterpret_cast<uint32_t*>(&l);
}

__device__ __forceinline__ void mma16816(float* c, const uint32_t* a,
                                         uint32_t b0, uint32_t b1) {
    asm volatile(
        "mma.sync.aligned.m16n8k16.row.col.f32.bf16.bf16.f32 "
        "{%0,%1,%2,%3}, {%4,%5,%6,%7}, {%8,%9}, {%0,%1,%2,%3};"
        : "+f"(c[0]), "+f"(c[1]), "+f"(c[2]), "+f"(c[3])
        : "r"(a[0]), "r"(a[1]), "r"(a[2]), "r"(a[3]), "r"(b0), "r"(b1));
}

__device__ __forceinline__ uint32_t sm_off(const void* p) {
    uint32_t a;
    asm("{ .reg .u64 t; cvta.to.shared.u64 t, %1; cvt.u32.u64 %0, t; }" : "=r"(a) : "l"(p));
    return a;
}

__device__ __forceinline__ void ldsm_x4(uint32_t& r0, uint32_t& r1,
                                        uint32_t& r2, uint32_t& r3, uint32_t addr) {
    asm volatile("ldmatrix.sync.aligned.m8n8.x4.shared.b16 {%0,%1,%2,%3}, [%4];"
                 : "=r"(r0), "=r"(r1), "=r"(r2), "=r"(r3) : "r"(addr));
}

// ---------------- init: zero CSR counters + convert all weights -------------
struct WConv {
    const float* in[6];
    __nv_bfloat16* hi[6];
    __nv_bfloat16* lo[6];
    int K[6], M[6];
    int off[7];
};

__global__ void init_misc(WConv a, int* __restrict__ deg, int* __restrict__ cursor,
                          int* __restrict__ cdeg, int* __restrict__ ccur,
                          float* __restrict__ colsq, int n, int nc)
{
    int gid = blockIdx.x * blockDim.x + threadIdx.x;
    if (gid < n) { deg[gid] = 0; cursor[gid] = 0; }
    if (gid < nc) { cdeg[gid] = 0; ccur[gid] = 0; }
    if (gid < 512) colsq[gid] = 0.f;
    if (gid < a.off[6]) {
        int s = 0;
#pragma unroll
        for (int i = 1; i < 6; i++) if (gid >= a.off[i]) s = i;
        int local = gid - a.off[s];
        int M = a.M[s], K = a.K[s];
        int k = local / M, m = local - k * M;
        float v = __ldg(a.in[s] + local);
        __nv_bfloat16 h = __float2bfloat16_rn(v);
        a.hi[s][m * K + k] = h;
        a.lo[s][m * K + k] = __float2bfloat16_rn(v - __bfloat162float(h));
    }
}

// ---------------- CSR build --------------------------------------------------
__global__ void hist_fused(const int* __restrict__ ei, int E,
                           const int* __restrict__ cluster, int n,
                           int* __restrict__ deg, int* __restrict__ cdeg)
{
    int gid = blockIdx.x * blockDim.x + threadIdx.x;
    if (gid < E) {
        atomicAdd(&deg[__ldg(ei + E + gid)], 1);
    } else if (gid < E + n) {
        atomicAdd(&cdeg[__ldg(cluster + gid - E)], 1);
    }
}

__global__ __launch_bounds__(512) void scan_block2(
    const int* __restrict__ inN, int* __restrict__ outN, int* __restrict__ sumsN, int n, int nbN,
    const int* __restrict__ inC, int* __restrict__ outC, int* __restrict__ sumsC, int nc)
{
    __shared__ int s[512];
    int tid = threadIdx.x;
    const int* in;  int* out; int* sums; int len; int blk;
    if ((int)blockIdx.x < nbN) { in = inN; out = outN; sums = sumsN; len = n;  blk = blockIdx.x; }
    else                       { in = inC; out = outC; sums = sumsC; len = nc; blk = blockIdx.x - nbN; }
    int i = blk * 512 + tid;
    int v = (i < len) ? in[i] : 0;
    s[tid] = v;
    __syncthreads();
#pragma unroll
    for (int off = 1; off < 512; off <<= 1) {
        int t = (tid >= off) ? s[tid - off] : 0;
        __syncthreads();
        s[tid] += t;
        __syncthreads();
    }
    if (i < len) out[i] = s[tid] - v;
    if (tid == 511) sums[blk] = s[511];
}

__global__ __launch_bounds__(512) void scan_add_fused(
    int* __restrict__ outN, const int* __restrict__ sumsN, int n, int nbN,
    int* __restrict__ outC, const int* __restrict__ sumsC, int nc)
{
    __shared__ int red[16];
    __shared__ int total;
    int tid = threadIdx.x;
    int* out; const int* sums; int len; int blk;
    if ((int)blockIdx.x < nbN) { out = outN; sums = sumsN; len = n;  blk = blockIdx.x; }
    else                       { out = outC; sums = sumsC; len = nc; blk = blockIdx.x - nbN; }
    int p = 0;
    for (int i = tid; i < blk; i += 512) p += sums[i];
#pragma unroll
    for (int off = 16; off >= 1; off >>= 1) p += __shfl_xor_sync(0xffffffffu, p, off);
    if ((tid & 31) == 0) red[tid >> 5] = p;
    __syncthreads();
    if (tid == 0) {
        int t = 0;
#pragma unroll
        for (int i = 0; i < 16; i++) t += red[i];
        total = t;
    }
    __syncthreads();
    int i = blk * 512 + tid;
    if (i < len) out[i] += total;
}

__global__ void scatter_fused(const int* __restrict__ ei, int E,
                              const int* __restrict__ cluster, int n,
                              const int* __restrict__ rowptr, int* __restrict__ cursor,
                              int* __restrict__ esrc,
                              const int* __restrict__ cptr, int* __restrict__ ccur,
                              int* __restrict__ cnodes)
{
    int gid = blockIdx.x * blockDim.x + threadIdx.x;
    if (gid < E) {
        int src = __ldg(ei + gid);
        int tgt = __ldg(ei + E + gid);
        int pos = rowptr[tgt] + atomicAdd(&cursor[tgt], 1);
        esrc[pos] = src;
    } else if (gid < E + n) {
        int i = gid - E;
        int cl = __ldg(cluster + i);
        int pos = cptr[cl] + atomicAdd(&ccur[cl], 1);
        cnodes[pos] = i;
    }
}

// ---------------- fused MLP layer: gemm1+bias+LN+ReLU+gemm2+bias ------------
// Ain [n, C] fp32; W1T [64][C] split bf16, W2T [C][64] split bf16
// Y [n, 2C] fp32: first C cols written here, rest by agg
template<int C>
__global__ __launch_bounds__(256) void fused_mlp(
    const float* __restrict__ Ain,
    const __nv_bfloat16* __restrict__ W1hi, const __nv_bfloat16* __restrict__ W1lo,
    const float* __restrict__ b1, const float* __restrict__ gam,
    const float* __restrict__ bet,
    const __nv_bfloat16* __restrict__ W2hi, const __nv_bfloat16* __restrict__ W2lo,
    const float* __restrict__ b2,
    float* __restrict__ Y, int n)
{
    constexpr int AS  = 72;
    constexpr int WS  = C + 8;
    constexpr int NKC = C / 64;
    constexpr int NG  = C / 64;
    constexpr int W1E = 64 * WS;
    constexpr int AE  = 128 * AS;
    extern __shared__ __align__(16) __nv_bfloat16 sm[];
    __nv_bfloat16* W1s0 = sm;
    __nv_bfloat16* W1s1 = sm + W1E;
    __nv_bfloat16* As0  = sm + 2 * W1E;
    __nv_bfloat16* As1  = As0 + AE;
    __nv_bfloat16* W2s0 = As1 + AE;
    __nv_bfloat16* W2s1 = W2s0 + C * AS;

    const int tid = threadIdx.x, wid = tid >> 5, lane = tid & 31;
    const int g = lane >> 2, q = lane & 3;
    const int r0b = blockIdx.x * 128;

    // load weights (both W1 and W2 up front — overlap with A staging)
    {
        constexpr int VPR = C / 8;
        for (int i = tid; i < 64 * VPR; i += 256) {
            int m = i / VPR, seg = i - m * VPR;
            *(uint4*)&W1s0[m * WS + seg * 8] = __ldg((const uint4*)(W1hi + (size_t)m * C) + seg);
            *(uint4*)&W1s1[m * WS + seg * 8] = __ldg((const uint4*)(W1lo + (size_t)m * C) + seg);
        }
        for (int i = tid; i < C * 8; i += 256) {
            int m = i >> 3, seg = i & 7;
            *(uint4*)&W2s0[m * AS + seg * 8] = __ldg((const uint4*)(W2hi + (size_t)m * 64) + seg);
            *(uint4*)&W2s1[m * AS + seg * 8] = __ldg((const uint4*)(W2lo + (size_t)m * 64) + seg);
        }
    }

    // per-thread ldmatrix address bases
    const int arow = wid * 16 + (lane & 15);
    const int acol = ((lane >> 4) & 1) * 8;
    const uint32_t a_hi = sm_off(As0 + arow * AS + acol);
    const uint32_t a_lo = sm_off(As1 + arow * AS + acol);
    const int brow = (lane & 7) + ((lane >> 4) << 3);
    const int bk8  = ((lane >> 3) & 1) * 8;
    const uint32_t w1h_b = sm_off(W1s0 + brow * WS + bk8);
    const uint32_t w1l_b = sm_off(W1s1 + brow * WS + bk8);
    const uint32_t w2h_b = sm_off(W2s0 + brow * AS + bk8);
    const uint32_t w2l_b = sm_off(W2s1 + brow * AS + bk8);

    float acc[8][4] = {};

    for (int kc = 0; kc < NKC; kc++) {
        __syncthreads();
        for (int i = tid; i < 128 * 32; i += 256) {
            int m = i >> 5, e = i & 31;
            int r = r0b + m;
            uint32_t h = 0, l = 0;
            if (r < n) {
                float2 v = __ldg((const float2*)Ain + (size_t)r * (C / 2) + kc * 32 + e);
                split2(v.x, v.y, h, l);
            }
            *(uint32_t*)&As0[m * AS + 2 * e] = h;
            *(uint32_t*)&As1[m * AS + 2 * e] = l;
        }
        __syncthreads();

#pragma unroll
        for (int ks = 0; ks < 4; ks++) {
            const int k0 = ks * 16;
            uint32_t ah[4], al[4];
            ldsm_x4(ah[0], ah[1], ah[2], ah[3], a_hi + k0 * 2);
            ldsm_x4(al[0], al[1], al[2], al[3], a_lo + k0 * 2);
            const int kg = kc * 64 + k0;
#pragma unroll
            for (int jj = 0; jj < 8; jj += 2) {
                uint32_t p0, p1, p2, p3, l0, l1, l2, l3;
                ldsm_x4(p0, p1, p2, p3, w1h_b + (8 * jj * WS + kg) * 2);
                ldsm_x4(l0, l1, l2, l3, w1l_b + (8 * jj * WS + kg) * 2);
                mma16816(acc[jj],     ah, p0, p1);
                mma16816(acc[jj],     ah, l0, l1);
                mma16816(acc[jj],     al, p0, p1);
                mma16816(acc[jj + 1], ah, p2, p3);
                mma16816(acc[jj + 1], ah, l2, l3);
                mma16816(acc[jj + 1], al, p2, p3);
            }
        }
    }

    // ---- gemm1 epilogue: bias + LN (quad shuffle) + ReLU -> H in As --------
    {
        float v0[16], v1[16];
        float s0 = 0.f, q0 = 0.f, s1 = 0.f, q1 = 0.f;
#pragma unroll
        for (int j = 0; j < 8; j++) {
            int c0 = 8*j + 2*q;
            float bx = __ldg(b1 + c0), by = __ldg(b1 + c0 + 1);
            float a = acc[j][0] + bx, b = acc[j][1] + by;
            float c = acc[j][2] + bx, d = acc[j][3] + by;
            v0[2*j] = a; v0[2*j+1] = b; v1[2*j] = c; v1[2*j+1] = d;
            s0 += a + b; q0 += a*a + b*b;
            s1 += c + d; q1 += c*c + d*d;
        }
#pragma unroll
        for (int off = 1; off < 4; off <<= 1) {
            s0 += __shfl_xor_sync(0xffffffffu, s0, off);
            q0 += __shfl_xor_sync(0xffffffffu, q0, off);
            s1 += __shfl_xor_sync(0xffffffffu, s1, off);
            q1 += __shfl_xor_sync(0xffffffffu, q1, off);
        }
        float mu0 = s0 * (1.f/64.f), var0 = q0 * (1.f/64.f) - mu0*mu0;
        float mu1 = s1 * (1.f/64.f), var1 = q1 * (1.f/64.f) - mu1*mu1;
        float rs0 = rsqrtf(var0 + LN_EPS), rs1 = rsqrtf(var1 + LN_EPS);
        __syncthreads();
        int rl0 = wid * 16 + g, rl1 = rl0 + 8;
#pragma unroll
        for (int j = 0; j < 8; j++) {
            int c0 = 8*j + 2*q;
            float ga = __ldg(gam + c0), gb = __ldg(gam + c0 + 1);
            float ba = __ldg(bet + c0), bb = __ldg(bet + c0 + 1);
            float f0 = fmaxf((v0[2*j]   - mu0) * rs0 * ga + ba, 0.f);
            float f1 = fmaxf((v0[2*j+1] - mu0) * rs0 * gb + bb, 0.f);
            float f2 = fmaxf((v1[2*j]   - mu1) * rs1 * ga + ba, 0.f);
            float f3 = fmaxf((v1[2*j+1] - mu1) * rs1 * gb + bb, 0.f);
            uint32_t h, l;
            split2(f0, f1, h, l);
            *(uint32_t*)&As0[rl0 * AS + c0] = h;
            *(uint32_t*)&As1[rl0 * AS + c0] = l;
            split2(f2, f3, h, l);
            *(uint32_t*)&As0[rl1 * AS + c0] = h;
            *(uint32_t*)&As1[rl1 * AS + c0] = l;
        }
    }
    __syncthreads();

    // ---- gemm2: H[128,64] @ W2 -> Y[:, 0:C] --------------------------------
    const int rg0 = r0b + wid * 16 + g;
    const int rg1 = rg0 + 8;

#pragma unroll
    for (int ng = 0; ng < NG; ng++) {
        float acc2[8][4] = {};
#pragma unroll
        for (int ks = 0; ks < 4; ks++) {
            const int k0 = ks * 16;
            uint32_t ah[4], al[4];
            ldsm_x4(ah[0], ah[1], ah[2], ah[3], a_hi + k0 * 2);
            ldsm_x4(al[0], al[1], al[2], al[3], a_lo + k0 * 2);
#pragma unroll
            for (int jj = 0; jj < 8; jj += 2) {
                uint32_t p0, p1, p2, p3, l0, l1, l2, l3;
                ldsm_x4(p0, p1, p2, p3, w2h_b + ((ng * 64 + 8 * jj) * AS + k0) * 2);
                ldsm_x4(l0, l1, l2, l3, w2l_b + ((ng * 64 + 8 * jj) * AS + k0) * 2);
                mma16816(acc2[jj],     ah, p0, p1);
                mma16816(acc2[jj],     ah, l0, l1);
                mma16816(acc2[jj],     al, p0, p1);
                mma16816(acc2[jj + 1], ah, p2, p3);
                mma16816(acc2[jj + 1], ah, l2, l3);
                mma16816(acc2[jj + 1], al, p2, p3);
            }
        }
        if (rg0 < n) {
            float2* orow = (float2*)(Y + (size_t)rg0 * (2 * C)) + ng * 32;
#pragma unroll
            for (int j = 0; j < 8; j++) {
                int c0 = 8*j + 2*q;
                orow[4*j + q] = make_float2(acc2[j][0] + __ldg(b2 + ng*64 + c0),
                                            acc2[j][1] + __ldg(b2 + ng*64 + c0 + 1));
            }
        }
        if (rg1 < n) {
            float2* orow = (float2*)(Y + (size_t)rg1 * (2 * C)) + ng * 32;
#pragma unroll
            for (int j = 0; j < 8; j++) {
                int c0 = 8*j + 2*q;
                orow[4*j + q] = make_float2(acc2[j][2] + __ldg(b2 + ng*64 + c0),
                                            acc2[j][3] + __ldg(b2 + ng*64 + c0 + 1));
            }
        }
    }
}

// ---------------- CSR gather-max aggregation (fp32, unrolled x4) ------------
template<int C>
__global__ __launch_bounds__(256) void agg_f(
    float* __restrict__ Y, const int* __restrict__ rowptr,
    const int* __restrict__ deg, const int* __restrict__ esrc, int n)
{
    int w = (blockIdx.x * blockDim.x + threadIdx.x) >> 5;
    if (w >= n) return;
    const int lane = threadIdx.x & 31;
    constexpr int EPL = C / 64;              // float2 entries per lane
    float2 mx[EPL];
#pragma unroll
    for (int i = 0; i < EPL; i++) mx[i] = make_float2(neg_inf(), neg_inf());
    int d = __ldg(deg + w), base = __ldg(rowptr + w);
    int j = 0;
    for (; j + 3 < d; j += 4) {
        int s0 = __ldg(esrc + base + j);
        int s1 = __ldg(esrc + base + j + 1);
        int s2 = __ldg(esrc + base + j + 2);
        int s3 = __ldg(esrc + base + j + 3);
        const float2* r0 = (const float2*)(Y + (size_t)s0 * (2 * C));
        const float2* r1 = (const float2*)(Y + (size_t)s1 * (2 * C));
        const float2* r2 = (const float2*)(Y + (size_t)s2 * (2 * C));
        const float2* r3 = (const float2*)(Y + (size_t)s3 * (2 * C));
#pragma unroll
        for (int i = 0; i < EPL; i++) {
            float2 v0 = __ldg(r0 + lane + i * 32);
            float2 v1 = __ldg(r1 + lane + i * 32);
            float2 v2 = __ldg(r2 + lane + i * 32);
            float2 v3 = __ldg(r3 + lane + i * 32);
            float ax = fmaxf(fmaxf(v0.x, v1.x), fmaxf(v2.x, v3.x));
            float ay = fmaxf(fmaxf(v0.y, v1.y), fmaxf(v2.y, v3.y));
            mx[i].x = fmaxf(mx[i].x, ax);
            mx[i].y = fmaxf(mx[i].y, ay);
        }
    }
    for (; j < d; j++) {
        int s0 = __ldg(esrc + base + j);
        const float2* r0 = (const float2*)(Y + (size_t)s0 * (2 * C));
#pragma unroll
        for (int i = 0; i < EPL; i++) {
            float2 v0 = __ldg(r0 + lane + i * 32);
            mx[i].x = fmaxf(mx[i].x, v0.x);
            mx[i].y = fmaxf(mx[i].y, v0.y);
        }
    }
    float2* orow = (float2*)(Y + (size_t)w * (2 * C) + C);
#pragma unroll
    for (int i = 0; i < EPL; i++)
        orow[lane + i * 32] = d ? mx[i] : make_float2(0.f, 0.f);
}

// ---------------- CSR cluster max-pool (fp32, unrolled x2) ------------------
__global__ __launch_bounds__(128) void pool_f(
    const float* __restrict__ Y, const int* __restrict__ cptr,
    const int* __restrict__ cdeg, const int* __restrict__ cnodes,
    float* __restrict__ out)
{
    int cl = blockIdx.x, t = threadIdx.x;
    int d = __ldg(cdeg + cl), base = __ldg(cptr + cl);
    float2 m0 = make_float2(neg_inf(), neg_inf());
    float2 m1 = m0;
    int j = 0;
    for (; j + 1 < d; j += 2) {
        int n0 = __ldg(cnodes + base + j);
        int n1 = __ldg(cnodes + base + j + 1);
        const float2* ra = (const float2*)(Y + (size_t)n0 * 512);
        const float2* rb = (const float2*)(Y + (size_t)n1 * 512);
        float2 a0 = __ldg(ra + t), a1 = __ldg(ra + t + 128);
        float2 b0 = __ldg(rb + t), b1 = __ldg(rb + t + 128);
        m0.x = fmaxf(m0.x, fmaxf(a0.x, b0.x)); m0.y = fmaxf(m0.y, fmaxf(a0.y, b0.y));
        m1.x = fmaxf(m1.x, fmaxf(a1.x, b1.x)); m1.y = fmaxf(m1.y, fmaxf(a1.y, b1.y));
    }
    if (j < d) {
        int n0 = __ldg(cnodes + base + j);
        const float2* ra = (const float2*)(Y + (size_t)n0 * 512);
        float2 a0 = __ldg(ra + t), a1 = __ldg(ra + t + 128);
        m0.x = fmaxf(m0.x, a0.x); m0.y = fmaxf(m0.y, a0.y);
        m1.x = fmaxf(m1.x, a1.x); m1.y = fmaxf(m1.y, a1.y);
    }
    if (!d) { m0 = make_float2(0.f, 0.f); m1 = m0; }
    float2* orow = (float2*)(out + (size_t)cl * 512);
    orow[t] = m0;
    orow[t + 128] = m1;
}

// ---------------- column L2 normalize ---------------------------------------
__global__ __launch_bounds__(512) void colsq_kernel(const float* __restrict__ out,
                                                    float* __restrict__ colsq, int nc)
{
    const int ROWS = 50;
    int c  = threadIdx.x;
    int r0 = blockIdx.x * ROWS;
    int r1 = min(r0 + ROWS, nc);
    float s = 0.f;
    for (int r = r0; r < r1; r++) {
        float f = out[(size_t)r * 512 + c];
        s += f * f;
    }
    atomicAdd(colsq + c, s);
}

__global__ void scale_kernel(float* __restrict__ out, const float* __restrict__ colsq, int nc)
{
    int gid = blockIdx.x * blockDim.x + threadIdx.x;        // over NC*128 float4s
    if (gid >= nc * 128) return;
    int c4 = gid & 127;
    float4 v = *(float4*)(out + (size_t)gid * 4);
    float4 s = *(const float4*)(colsq + c4 * 4);
    v.x *= rsqrtf(s.x); v.y *= rsqrtf(s.y);
    v.z *= rsqrtf(s.z); v.w *= rsqrtf(s.w);
    *(float4*)(out + (size_t)gid * 4) = v;
}

// ---------------- launch ----------------------------------------------------
extern "C" void kernel_launch(void* const* d_in, const int* in_sizes, int n_in,
                              void* d_out, int out_size)
{
    const float* x       = (const float*)d_in[0];
    const int*   ei      = (const int*)d_in[1];
    const int*   cluster = (const int*)d_in[2];
    const int N  = in_sizes[0] / 64;
    const int E  = in_sizes[1] / 2;
    const int NC = out_size / 512;
    float* out = (float*)d_out;

    float *y0, *y1, *y2, *colsq;
    __nv_bfloat16 *w1h[3], *w1l[3], *w2h[3], *w2l[3];
    int *deg, *rowptr, *cursor, *esrc, *cdeg, *cptr, *ccur, *cnodes, *bsumsN, *bsumsC;
    cudaGetSymbolAddress((void**)&y0, g_y0);
    cudaGetSymbolAddress((void**)&y1, g_y1);
    cudaGetSymbolAddress((void**)&y2, g_y2);
    cudaGetSymbolAddress((void**)&w1h[0], g_w1thi0); cudaGetSymbolAddress((void**)&w1l[0], g_w1tlo0);
    cudaGetSymbolAddress((void**)&w1h[1], g_w1thi1); cudaGetSymbolAddress((void**)&w1l[1], g_w1tlo1);
    cudaGetSymbolAddress((void**)&w1h[2], g_w1thi2); cudaGetSymbolAddress((void**)&w1l[2], g_w1tlo2);
    cudaGetSymbolAddress((void**)&w2h[0], g_w2thi0); cudaGetSymbolAddress((void**)&w2l[0], g_w2tlo0);
    cudaGetSymbolAddress((void**)&w2h[1], g_w2thi1); cudaGetSymbolAddress((void**)&w2l[1], g_w2tlo1);
    cudaGetSymbolAddress((void**)&w2h[2], g_w2thi2); cudaGetSymbolAddress((void**)&w2l[2], g_w2tlo2);
    cudaGetSymbolAddress((void**)&colsq,  g_colsq);
    cudaGetSymbolAddress((void**)&deg,    g_deg);
    cudaGetSymbolAddress((void**)&rowptr, g_rowptr);
    cudaGetSymbolAddress((void**)&cursor, g_cursor);
    cudaGetSymbolAddress((void**)&esrc,   g_esrc);
    cudaGetSymbolAddress((void**)&cdeg,   g_cdeg);
    cudaGetSymbolAddress((void**)&cptr,   g_cptr);
    cudaGetSymbolAddress((void**)&ccur,   g_ccur);
    cudaGetSymbolAddress((void**)&cnodes, g_cnodes);
    cudaGetSymbolAddress((void**)&bsumsN, g_bsumsN);
    cudaGetSymbolAddress((void**)&bsumsC, g_bsumsC);

    // smem (R8 layout: W1 + A + W2 all resident)
    const int SM64  = 2 * (64*72  + 128*72 + 64*72 ) * 2;   //  73728
    const int SM128 = 2 * (64*136 + 128*72 + 128*72) * 2;   // 108544
    const int SM256 = 2 * (64*264 + 128*72 + 256*72) * 2;   // 178176
    cudaFuncSetAttribute((const void*)fused_mlp<64>,  cudaFuncAttributeMaxDynamicSharedMemorySize, SM64);
    cudaFuncSetAttribute((const void*)fused_mlp<128>, cudaFuncAttributeMaxDynamicSharedMemorySize, SM128);
    cudaFuncSetAttribute((const void*)fused_mlp<256>, cudaFuncAttributeMaxDynamicSharedMemorySize, SM256);

    const int GRID = (N + 127) / 128;
    const int nbN = (N + 511) / 512;
    const int nbC = (NC + 511) / 512;

    // ---- init: zero counters + weight conversion (1 launch) ----
    {
        WConv a;
        int off = 0;
        const int CINs[3] = {64, 128, 256};
        for (int i = 0; i < 3; i++) {
            int c = CINs[i];
            a.in[2*i]   = (const float*)d_in[3 + 6*i];       // W1 [c][64] -> [64][c]
            a.hi[2*i]   = w1h[i]; a.lo[2*i] = w1l[i];
            a.K[2*i]    = c;  a.M[2*i] = 64;
            a.off[2*i]  = off; off += c * 64;
            a.in[2*i+1] = (const float*)d_in[3 + 6*i + 4];   // W2 [64][c] -> [c][64]
            a.hi[2*i+1] = w2h[i]; a.lo[2*i+1] = w2l[i];
            a.K[2*i+1]  = 64; a.M[2*i+1] = c;
            a.off[2*i+1] = off; off += 64 * c;
        }
        a.off[6] = off;
        int span = N > off ? N : off;
        init_misc<<<(span + 255) / 256, 256>>>(a, deg, cursor, cdeg, ccur, colsq, N, NC);
    }

    // ---- CSR build (4 launches) ----
    hist_fused<<<(E + N + 255) / 256, 256>>>(ei, E, cluster, N, deg, cdeg);
    scan_block2<<<nbN + nbC, 512>>>(deg, rowptr, bsumsN, N, nbN, cdeg, cptr, bsumsC, NC);
    scan_add_fused<<<nbN + nbC, 512>>>(rowptr, bsumsN, N, nbN, cptr, bsumsC, NC);
    scatter_fused<<<(E + N + 255) / 256, 256>>>(ei, E, cluster, N, rowptr, cursor, esrc,
                                                cptr, ccur, cnodes);

    // ---- layers ----
    fused_mlp<64><<<GRID, 256, SM64>>>(
        x, w1h[0], w1l[0], (const float*)d_in[4], (const float*)d_in[5],
        (const float*)d_in[6], w2h[0], w2l[0], (const float*)d_in[8], y0, N);
    agg_f<64><<<(N + 7) / 8, 256>>>(y0, rowptr, deg, esrc, N);

    fused_mlp<128><<<GRID, 256, SM128>>>(
        y0, w1h[1], w1l[1], (const float*)d_in[10], (const float*)d_in[11],
        (const float*)d_in[12], w2h[1], w2l[1], (const float*)d_in[14], y1, N);
    agg_f<128><<<(N + 7) / 8, 256>>>(y1, rowptr, deg, esrc, N);

    fused_mlp<256><<<GRID, 256, SM256>>>(
        y1, w1h[2], w1l[2], (const float*)d_in[16], (const float*)d_in[17],
        (const float*)d_in[18], w2h[2], w2l[2], (const float*)d_in[20], y2, N);
    agg_f<256><<<(N + 7) / 8, 256>>>(y2, rowptr, deg, esrc, N);

    // ---- cluster max-pool + column L2 normalize ----
    pool_f<<<NC, 128>>>(y2, cptr, cdeg, cnodes, out);
    colsq_kernel<<<(NC + 49) / 50, 512>>>(out, colsq, NC);
    scale_kernel<<<(NC * 128 + 255) / 256, 256>>>(out, colsq, NC);
}

// round 11
// speedup vs baseline: 1.3052x; 1.0456x over previous
#include <cuda_runtime.h>
#include <cuda_bf16.h>
#include <cstdint>

#define LN_EPS 1e-5f

// ---------------- scratch (device globals: allocation-free) ----------------
__device__ __align__(128) float g_y0[100000 * 128];
__device__ __align__(128) float g_y1[100000 * 256];
__device__ __align__(128) float g_y2[100000 * 256];   // layer2 GEMM out only (no agg half)
__device__ __align__(128) __nv_bfloat16 g_w1thi0[64*64],  g_w1tlo0[64*64];
__device__ __align__(128) __nv_bfloat16 g_w1thi1[64*128], g_w1tlo1[64*128];
__device__ __align__(128) __nv_bfloat16 g_w1thi2[64*256], g_w1tlo2[64*256];
__device__ __align__(128) __nv_bfloat16 g_w2thi0[64*64],  g_w2tlo0[64*64];
__device__ __align__(128) __nv_bfloat16 g_w2thi1[128*64], g_w2tlo1[128*64];
__device__ __align__(128) __nv_bfloat16 g_w2thi2[256*64], g_w2tlo2[256*64];
__device__ float g_colsq[512];

// CSR scratch
__device__ int g_deg[100000];
__device__ int g_rowptr[100000];
__device__ int g_cursor[100000];
__device__ int g_esrc[800000];
__device__ int g_cdeg[10000];
__device__ int g_cptr[10000];
__device__ int g_ccur[10000];
__device__ int g_cnodes[100000];
__device__ int g_bsumsN[512];
__device__ int g_bsumsC[512];

__device__ __forceinline__ float neg_inf() { return __int_as_float(0xff800000); }

__device__ __forceinline__ void split2(float a, float b, uint32_t& hi, uint32_t& lo) {
    __nv_bfloat16 ah = __float2bfloat16_rn(a);
    __nv_bfloat16 bh = __float2bfloat16_rn(b);
    __nv_bfloat16 al = __float2bfloat16_rn(a - __bfloat162float(ah));
    __nv_bfloat16 bl = __float2bfloat16_rn(b - __bfloat162float(bh));
    __nv_bfloat162 h = __halves2bfloat162(ah, bh);
    __nv_bfloat162 l = __halves2bfloat162(al, bl);
    hi = *reinterpret_cast<uint32_t*>(&h);
    lo = *reinterpret_cast<uint32_t*>(&l);
}

__device__ __forceinline__ void mma16816(float* c, const uint32_t* a,
                                         uint32_t b0, uint32_t b1) {
    asm volatile(
        "mma.sync.aligned.m16n8k16.row.col.f32.bf16.bf16.f32 "
        "{%0,%1,%2,%3}, {%4,%5,%6,%7}, {%8,%9}, {%0,%1,%2,%3};"
        : "+f"(c[0]), "+f"(c[1]), "+f"(c[2]), "+f"(c[3])
        : "r"(a[0]), "r"(a[1]), "r"(a[2]), "r"(a[3]), "r"(b0), "r"(b1));
}

__device__ __forceinline__ uint32_t sm_off(const void* p) {
    uint32_t a;
    asm("{ .reg .u64 t; cvta.to.shared.u64 t, %1; cvt.u32.u64 %0, t; }" : "=r"(a) : "l"(p));
    return a;
}

__device__ __forceinline__ void ldsm_x4(uint32_t& r0, uint32_t& r1,
                                        uint32_t& r2, uint32_t& r3, uint32_t addr) {
    asm volatile("ldmatrix.sync.aligned.m8n8.x4.shared.b16 {%0,%1,%2,%3}, [%4];"
                 : "=r"(r0), "=r"(r1), "=r"(r2), "=r"(r3) : "r"(addr));
}

// ---------------- init: zero CSR counters + convert all weights -------------
struct WConv {
    const float* in[6];
    __nv_bfloat16* hi[6];
    __nv_bfloat16* lo[6];
    int K[6], M[6];
    int off[7];
};

__global__ void init_misc(WConv a, int* __restrict__ deg, int* __restrict__ cursor,
                          int* __restrict__ cdeg, int* __restrict__ ccur,
                          float* __restrict__ colsq, int n, int nc)
{
    int gid = blockIdx.x * blockDim.x + threadIdx.x;
    if (gid < n) { deg[gid] = 0; cursor[gid] = 0; }
    if (gid < nc) { cdeg[gid] = 0; ccur[gid] = 0; }
    if (gid < 512) colsq[gid] = 0.f;
    if (gid < a.off[6]) {
        int s = 0;
#pragma unroll
        for (int i = 1; i < 6; i++) if (gid >= a.off[i]) s = i;
        int local = gid - a.off[s];
        int M = a.M[s], K = a.K[s];
        int k = local / M, m = local - k * M;
        float v = __ldg(a.in[s] + local);
        __nv_bfloat16 h = __float2bfloat16_rn(v);
        a.hi[s][m * K + k] = h;
        a.lo[s][m * K + k] = __float2bfloat16_rn(v - __bfloat162float(h));
    }
}

// ---------------- CSR build --------------------------------------------------
__global__ void hist_fused(const int* __restrict__ ei, int E,
                           const int* __restrict__ cluster, int n,
                           int* __restrict__ deg, int* __restrict__ cdeg)
{
    int gid = blockIdx.x * blockDim.x + threadIdx.x;
    if (gid < E) {
        atomicAdd(&deg[__ldg(ei + E + gid)], 1);
    } else if (gid < E + n) {
        atomicAdd(&cdeg[__ldg(cluster + gid - E)], 1);
    }
}

__global__ __launch_bounds__(512) void scan_block2(
    const int* __restrict__ inN, int* __restrict__ outN, int* __restrict__ sumsN, int n, int nbN,
    const int* __restrict__ inC, int* __restrict__ outC, int* __restrict__ sumsC, int nc)
{
    __shared__ int s[512];
    int tid = threadIdx.x;
    const int* in;  int* out; int* sums; int len; int blk;
    if ((int)blockIdx.x < nbN) { in = inN; out = outN; sums = sumsN; len = n;  blk = blockIdx.x; }
    else                       { in = inC; out = outC; sums = sumsC; len = nc; blk = blockIdx.x - nbN; }
    int i = blk * 512 + tid;
    int v = (i < len) ? in[i] : 0;
    s[tid] = v;
    __syncthreads();
#pragma unroll
    for (int off = 1; off < 512; off <<= 1) {
        int t = (tid >= off) ? s[tid - off] : 0;
        __syncthreads();
        s[tid] += t;
        __syncthreads();
    }
    if (i < len) out[i] = s[tid] - v;
    if (tid == 511) sums[blk] = s[511];
}

__global__ __launch_bounds__(512) void scan_add_fused(
    int* __restrict__ outN, const int* __restrict__ sumsN, int n, int nbN,
    int* __restrict__ outC, const int* __restrict__ sumsC, int nc)
{
    __shared__ int red[16];
    __shared__ int total;
    int tid = threadIdx.x;
    int* out; const int* sums; int len; int blk;
    if ((int)blockIdx.x < nbN) { out = outN; sums = sumsN; len = n;  blk = blockIdx.x; }
    else                       { out = outC; sums = sumsC; len = nc; blk = blockIdx.x - nbN; }
    int p = 0;
    for (int i = tid; i < blk; i += 512) p += sums[i];
#pragma unroll
    for (int off = 16; off >= 1; off >>= 1) p += __shfl_xor_sync(0xffffffffu, p, off);
    if ((tid & 31) == 0) red[tid >> 5] = p;
    __syncthreads();
    if (tid == 0) {
        int t = 0;
#pragma unroll
        for (int i = 0; i < 16; i++) t += red[i];
        total = t;
    }
    __syncthreads();
    int i = blk * 512 + tid;
    if (i < len) out[i] += total;
}

__global__ void scatter_fused(const int* __restrict__ ei, int E,
                              const int* __restrict__ cluster, int n,
                              const int* __restrict__ rowptr, int* __restrict__ cursor,
                              int* __restrict__ esrc,
                              const int* __restrict__ cptr, int* __restrict__ ccur,
                              int* __restrict__ cnodes)
{
    int gid = blockIdx.x * blockDim.x + threadIdx.x;
    if (gid < E) {
        int src = __ldg(ei + gid);
        int tgt = __ldg(ei + E + gid);
        int pos = rowptr[tgt] + atomicAdd(&cursor[tgt], 1);
        esrc[pos] = src;
    } else if (gid < E + n) {
        int i = gid - E;
        int cl = __ldg(cluster + i);
        int pos = cptr[cl] + atomicAdd(&ccur[cl], 1);
        cnodes[pos] = i;
    }
}

// ---------------- fused MLP layer: gemm1+bias+LN+ReLU+gemm2+bias ------------
// Ain [n, C] fp32; W1T [64][C] split bf16, W2T [C][64] split bf16
// Y row stride OS floats; first C cols written here
template<int C, int OS>
__global__ __launch_bounds__(256) void fused_mlp(
    const float* __restrict__ Ain,
    const __nv_bfloat16* __restrict__ W1hi, const __nv_bfloat16* __restrict__ W1lo,
    const float* __restrict__ b1, const float* __restrict__ gam,
    const float* __restrict__ bet,
    const __nv_bfloat16* __restrict__ W2hi, const __nv_bfloat16* __restrict__ W2lo,
    const float* __restrict__ b2,
    float* __restrict__ Y, int n)
{
    constexpr int AS  = 72;
    constexpr int WS  = C + 8;
    constexpr int NKC = C / 64;
    constexpr int NG  = C / 64;
    constexpr int W1E = 64 * WS;
    constexpr int AE  = 128 * AS;
    extern __shared__ __align__(16) __nv_bfloat16 sm[];
    __nv_bfloat16* W1s0 = sm;
    __nv_bfloat16* W1s1 = sm + W1E;
    __nv_bfloat16* As0  = sm + 2 * W1E;
    __nv_bfloat16* As1  = As0 + AE;
    __nv_bfloat16* W2s0 = As1 + AE;
    __nv_bfloat16* W2s1 = W2s0 + C * AS;

    const int tid = threadIdx.x, wid = tid >> 5, lane = tid & 31;
    const int g = lane >> 2, q = lane & 3;
    const int r0b = blockIdx.x * 128;

    // load weights (W1 + W2 up front)
    {
        constexpr int VPR = C / 8;
        for (int i = tid; i < 64 * VPR; i += 256) {
            int m = i / VPR, seg = i - m * VPR;
            *(uint4*)&W1s0[m * WS + seg * 8] = __ldg((const uint4*)(W1hi + (size_t)m * C) + seg);
            *(uint4*)&W1s1[m * WS + seg * 8] = __ldg((const uint4*)(W1lo + (size_t)m * C) + seg);
        }
        for (int i = tid; i < C * 8; i += 256) {
            int m = i >> 3, seg = i & 7;
            *(uint4*)&W2s0[m * AS + seg * 8] = __ldg((const uint4*)(W2hi + (size_t)m * 64) + seg);
            *(uint4*)&W2s1[m * AS + seg * 8] = __ldg((const uint4*)(W2lo + (size_t)m * 64) + seg);
        }
    }

    // per-thread ldmatrix address bases
    const int arow = wid * 16 + (lane & 15);
    const int acol = ((lane >> 4) & 1) * 8;
    const uint32_t a_hi = sm_off(As0 + arow * AS + acol);
    const uint32_t a_lo = sm_off(As1 + arow * AS + acol);
    const int brow = (lane & 7) + ((lane >> 4) << 3);
    const int bk8  = ((lane >> 3) & 1) * 8;
    const uint32_t w1h_b = sm_off(W1s0 + brow * WS + bk8);
    const uint32_t w1l_b = sm_off(W1s1 + brow * WS + bk8);
    const uint32_t w2h_b = sm_off(W2s0 + brow * AS + bk8);
    const uint32_t w2l_b = sm_off(W2s1 + brow * AS + bk8);

    float acc[8][4] = {};

    for (int kc = 0; kc < NKC; kc++) {
        __syncthreads();
        for (int i = tid; i < 128 * 32; i += 256) {
            int m = i >> 5, e = i & 31;
            int r = r0b + m;
            uint32_t h = 0, l = 0;
            if (r < n) {
                float2 v = __ldg((const float2*)Ain + (size_t)r * (C / 2) + kc * 32 + e);
                split2(v.x, v.y, h, l);
            }
            *(uint32_t*)&As0[m * AS + 2 * e] = h;
            *(uint32_t*)&As1[m * AS + 2 * e] = l;
        }
        __syncthreads();

#pragma unroll
        for (int ks = 0; ks < 4; ks++) {
            const int k0 = ks * 16;
            uint32_t ah[4], al[4];
            ldsm_x4(ah[0], ah[1], ah[2], ah[3], a_hi + k0 * 2);
            ldsm_x4(al[0], al[1], al[2], al[3], a_lo + k0 * 2);
            const int kg = kc * 64 + k0;
#pragma unroll
            for (int jj = 0; jj < 8; jj += 2) {
                uint32_t p0, p1, p2, p3, l0, l1, l2, l3;
                ldsm_x4(p0, p1, p2, p3, w1h_b + (8 * jj * WS + kg) * 2);
                ldsm_x4(l0, l1, l2, l3, w1l_b + (8 * jj * WS + kg) * 2);
                mma16816(acc[jj],     ah, p0, p1);
                mma16816(acc[jj],     ah, l0, l1);
                mma16816(acc[jj],     al, p0, p1);
                mma16816(acc[jj + 1], ah, p2, p3);
                mma16816(acc[jj + 1], ah, l2, l3);
                mma16816(acc[jj + 1], al, p2, p3);
            }
        }
    }

    // ---- gemm1 epilogue: bias + LN (quad shuffle) + ReLU -> H in As --------
    {
        float v0[16], v1[16];
        float s0 = 0.f, q0 = 0.f, s1 = 0.f, q1 = 0.f;
#pragma unroll
        for (int j = 0; j < 8; j++) {
            int c0 = 8*j + 2*q;
            float bx = __ldg(b1 + c0), by = __ldg(b1 + c0 + 1);
            float a = acc[j][0] + bx, b = acc[j][1] + by;
            float c = acc[j][2] + bx, d = acc[j][3] + by;
            v0[2*j] = a; v0[2*j+1] = b; v1[2*j] = c; v1[2*j+1] = d;
            s0 += a + b; q0 += a*a + b*b;
            s1 += c + d; q1 += c*c + d*d;
        }
#pragma unroll
        for (int off = 1; off < 4; off <<= 1) {
            s0 += __shfl_xor_sync(0xffffffffu, s0, off);
            q0 += __shfl_xor_sync(0xffffffffu, q0, off);
            s1 += __shfl_xor_sync(0xffffffffu, s1, off);
            q1 += __shfl_xor_sync(0xffffffffu, q1, off);
        }
        float mu0 = s0 * (1.f/64.f), var0 = q0 * (1.f/64.f) - mu0*mu0;
        float mu1 = s1 * (1.f/64.f), var1 = q1 * (1.f/64.f) - mu1*mu1;
        float rs0 = rsqrtf(var0 + LN_EPS), rs1 = rsqrtf(var1 + LN_EPS);
        __syncthreads();
        int rl0 = wid * 16 + g, rl1 = rl0 + 8;
#pragma unroll
        for (int j = 0; j < 8; j++) {
            int c0 = 8*j + 2*q;
            float ga = __ldg(gam + c0), gb = __ldg(gam + c0 + 1);
            float ba = __ldg(bet + c0), bb = __ldg(bet + c0 + 1);
            float f0 = fmaxf((v0[2*j]   - mu0) * rs0 * ga + ba, 0.f);
            float f1 = fmaxf((v0[2*j+1] - mu0) * rs0 * gb + bb, 0.f);
            float f2 = fmaxf((v1[2*j]   - mu1) * rs1 * ga + ba, 0.f);
            float f3 = fmaxf((v1[2*j+1] - mu1) * rs1 * gb + bb, 0.f);
            uint32_t h, l;
            split2(f0, f1, h, l);
            *(uint32_t*)&As0[rl0 * AS + c0] = h;
            *(uint32_t*)&As1[rl0 * AS + c0] = l;
            split2(f2, f3, h, l);
            *(uint32_t*)&As0[rl1 * AS + c0] = h;
            *(uint32_t*)&As1[rl1 * AS + c0] = l;
        }
    }
    __syncthreads();

    // ---- gemm2: H[128,64] @ W2 -> Y[:, 0:C] --------------------------------
    const int rg0 = r0b + wid * 16 + g;
    const int rg1 = rg0 + 8;

#pragma unroll
    for (int ng = 0; ng < NG; ng++) {
        float acc2[8][4] = {};
#pragma unroll
        for (int ks = 0; ks < 4; ks++) {
            const int k0 = ks * 16;
            uint32_t ah[4], al[4];
            ldsm_x4(ah[0], ah[1], ah[2], ah[3], a_hi + k0 * 2);
            ldsm_x4(al[0], al[1], al[2], al[3], a_lo + k0 * 2);
#pragma unroll
            for (int jj = 0; jj < 8; jj += 2) {
                uint32_t p0, p1, p2, p3, l0, l1, l2, l3;
                ldsm_x4(p0, p1, p2, p3, w2h_b + ((ng * 64 + 8 * jj) * AS + k0) * 2);
                ldsm_x4(l0, l1, l2, l3, w2l_b + ((ng * 64 + 8 * jj) * AS + k0) * 2);
                mma16816(acc2[jj],     ah, p0, p1);
                mma16816(acc2[jj],     ah, l0, l1);
                mma16816(acc2[jj],     al, p0, p1);
                mma16816(acc2[jj + 1], ah, p2, p3);
                mma16816(acc2[jj + 1], ah, l2, l3);
                mma16816(acc2[jj + 1], al, p2, p3);
            }
        }
        if (rg0 < n) {
            float2* orow = (float2*)(Y + (size_t)rg0 * OS) + ng * 32;
#pragma unroll
            for (int j = 0; j < 8; j++) {
                int c0 = 8*j + 2*q;
                orow[4*j + q] = make_float2(acc2[j][0] + __ldg(b2 + ng*64 + c0),
                                            acc2[j][1] + __ldg(b2 + ng*64 + c0 + 1));
            }
        }
        if (rg1 < n) {
            float2* orow = (float2*)(Y + (size_t)rg1 * OS) + ng * 32;
#pragma unroll
            for (int j = 0; j < 8; j++) {
                int c0 = 8*j + 2*q;
                orow[4*j + q] = make_float2(acc2[j][2] + __ldg(b2 + ng*64 + c0),
                                            acc2[j][3] + __ldg(b2 + ng*64 + c0 + 1));
            }
        }
    }
}

// ---------------- CSR gather-max aggregation (fp32, unrolled x4) ------------
template<int C>
__global__ __launch_bounds__(256) void agg_f(
    float* __restrict__ Y, const int* __restrict__ rowptr,
    const int* __restrict__ deg, const int* __restrict__ esrc, int n)
{
    int w = (blockIdx.x * blockDim.x + threadIdx.x) >> 5;
    if (w >= n) return;
    const int lane = threadIdx.x & 31;
    constexpr int EPL = C / 64;
    float2 mx[EPL];
#pragma unroll
    for (int i = 0; i < EPL; i++) mx[i] = make_float2(neg_inf(), neg_inf());
    int d = __ldg(deg + w), base = __ldg(rowptr + w);
    int j = 0;
    for (; j + 3 < d; j += 4) {
        int s0 = __ldg(esrc + base + j);
        int s1 = __ldg(esrc + base + j + 1);
        int s2 = __ldg(esrc + base + j + 2);
        int s3 = __ldg(esrc + base + j + 3);
        const float2* r0 = (const float2*)(Y + (size_t)s0 * (2 * C));
        const float2* r1 = (const float2*)(Y + (size_t)s1 * (2 * C));
        const float2* r2 = (const float2*)(Y + (size_t)s2 * (2 * C));
        const float2* r3 = (const float2*)(Y + (size_t)s3 * (2 * C));
#pragma unroll
        for (int i = 0; i < EPL; i++) {
            float2 v0 = __ldg(r0 + lane + i * 32);
            float2 v1 = __ldg(r1 + lane + i * 32);
            float2 v2 = __ldg(r2 + lane + i * 32);
            float2 v3 = __ldg(r3 + lane + i * 32);
            float ax = fmaxf(fmaxf(v0.x, v1.x), fmaxf(v2.x, v3.x));
            float ay = fmaxf(fmaxf(v0.y, v1.y), fmaxf(v2.y, v3.y));
            mx[i].x = fmaxf(mx[i].x, ax);
            mx[i].y = fmaxf(mx[i].y, ay);
        }
    }
    for (; j < d; j++) {
        int s0 = __ldg(esrc + base + j);
        const float2* r0 = (const float2*)(Y + (size_t)s0 * (2 * C));
#pragma unroll
        for (int i = 0; i < EPL; i++) {
            float2 v0 = __ldg(r0 + lane + i * 32);
            mx[i].x = fmaxf(mx[i].x, v0.x);
            mx[i].y = fmaxf(mx[i].y, v0.y);
        }
    }
    float2* orow = (float2*)(Y + (size_t)w * (2 * C) + C);
#pragma unroll
    for (int i = 0; i < EPL; i++)
        orow[lane + i * 32] = d ? mx[i] : make_float2(0.f, 0.f);
}

// ---------------- fused layer-2 agg + cluster max-pool ----------------------
// Y [n, 256] (layer2 GEMM out). Per cluster:
//   out first 256  = max over nodes nd of Y[nd]
//   out second 256 = max over in-edges (s -> nd in cluster) of Y[s],
//                    clamped with 0 if any member node has deg==0; 0 if empty
__global__ __launch_bounds__(128) void pool_agg(
    const float* __restrict__ Y,
    const int* __restrict__ cptr, const int* __restrict__ cdeg,
    const int* __restrict__ cnodes,
    const int* __restrict__ rowptr, const int* __restrict__ deg,
    const int* __restrict__ esrc,
    float* __restrict__ out)
{
    int cl = blockIdx.x, t = threadIdx.x;
    int cd = __ldg(cdeg + cl), cbase = __ldg(cptr + cl);
    float2 m0 = make_float2(neg_inf(), neg_inf());
    float2 m1 = m0;
    bool zerodeg = false;
    for (int j = 0; j < cd; j++) {
        int nd = __ldg(cnodes + cbase + j);
        const float2* row = (const float2*)(Y + (size_t)nd * 256);
        float2 v = __ldg(row + t);
        m0.x = fmaxf(m0.x, v.x); m0.y = fmaxf(m0.y, v.y);
        int d = __ldg(deg + nd), eb = __ldg(rowptr + nd);
        if (d == 0) zerodeg = true;
        int e = 0;
        for (; e + 1 < d; e += 2) {
            int s0 = __ldg(esrc + eb + e);
            int s1 = __ldg(esrc + eb + e + 1);
            float2 w0 = __ldg((const float2*)(Y + (size_t)s0 * 256) + t);
            float2 w1 = __ldg((const float2*)(Y + (size_t)s1 * 256) + t);
            m1.x = fmaxf(m1.x, fmaxf(w0.x, w1.x));
            m1.y = fmaxf(m1.y, fmaxf(w0.y, w1.y));
        }
        if (e < d) {
            int s0 = __ldg(esrc + eb + e);
            float2 w0 = __ldg((const float2*)(Y + (size_t)s0 * 256) + t);
            m1.x = fmaxf(m1.x, w0.x);
            m1.y = fmaxf(m1.y, w0.y);
        }
    }
    if (cd == 0) {
        m0 = make_float2(0.f, 0.f);
        m1 = m0;
    } else if (zerodeg) {
        m1.x = fmaxf(m1.x, 0.f);
        m1.y = fmaxf(m1.y, 0.f);
    }
    float2* orow = (float2*)(out + (size_t)cl * 512);
    orow[t] = m0;
    orow[t + 128] = m1;
}

// ---------------- column L2 normalize ---------------------------------------
__global__ __launch_bounds__(512) void colsq_kernel(const float* __restrict__ out,
                                                    float* __restrict__ colsq, int nc)
{
    const int ROWS = 50;
    int c  = threadIdx.x;
    int r0 = blockIdx.x * ROWS;
    int r1 = min(r0 + ROWS, nc);
    float s = 0.f;
    for (int r = r0; r < r1; r++) {
        float f = out[(size_t)r * 512 + c];
        s += f * f;
    }
    atomicAdd(colsq + c, s);
}

__global__ void scale_kernel(float* __restrict__ out, const float* __restrict__ colsq, int nc)
{
    int gid = blockIdx.x * blockDim.x + threadIdx.x;        // over NC*128 float4s
    if (gid >= nc * 128) return;
    int c4 = gid & 127;
    float4 v = *(float4*)(out + (size_t)gid * 4);
    float4 s = *(const float4*)(colsq + c4 * 4);
    v.x *= rsqrtf(s.x); v.y *= rsqrtf(s.y);
    v.z *= rsqrtf(s.z); v.w *= rsqrtf(s.w);
    *(float4*)(out + (size_t)gid * 4) = v;
}

// ---------------- launch ----------------------------------------------------
extern "C" void kernel_launch(void* const* d_in, const int* in_sizes, int n_in,
                              void* d_out, int out_size)
{
    const float* x       = (const float*)d_in[0];
    const int*   ei      = (const int*)d_in[1];
    const int*   cluster = (const int*)d_in[2];
    const int N  = in_sizes[0] / 64;
    const int E  = in_sizes[1] / 2;
    const int NC = out_size / 512;
    float* out = (float*)d_out;

    float *y0, *y1, *y2, *colsq;
    __nv_bfloat16 *w1h[3], *w1l[3], *w2h[3], *w2l[3];
    int *deg, *rowptr, *cursor, *esrc, *cdeg, *cptr, *ccur, *cnodes, *bsumsN, *bsumsC;
    cudaGetSymbolAddress((void**)&y0, g_y0);
    cudaGetSymbolAddress((void**)&y1, g_y1);
    cudaGetSymbolAddress((void**)&y2, g_y2);
    cudaGetSymbolAddress((void**)&w1h[0], g_w1thi0); cudaGetSymbolAddress((void**)&w1l[0], g_w1tlo0);
    cudaGetSymbolAddress((void**)&w1h[1], g_w1thi1); cudaGetSymbolAddress((void**)&w1l[1], g_w1tlo1);
    cudaGetSymbolAddress((void**)&w1h[2], g_w1thi2); cudaGetSymbolAddress((void**)&w1l[2], g_w1tlo2);
    cudaGetSymbolAddress((void**)&w2h[0], g_w2thi0); cudaGetSymbolAddress((void**)&w2l[0], g_w2tlo0);
    cudaGetSymbolAddress((void**)&w2h[1], g_w2thi1); cudaGetSymbolAddress((void**)&w2l[1], g_w2tlo1);
    cudaGetSymbolAddress((void**)&w2h[2], g_w2thi2); cudaGetSymbolAddress((void**)&w2l[2], g_w2tlo2);
    cudaGetSymbolAddress((void**)&colsq,  g_colsq);
    cudaGetSymbolAddress((void**)&deg,    g_deg);
    cudaGetSymbolAddress((void**)&rowptr, g_rowptr);
    cudaGetSymbolAddress((void**)&cursor, g_cursor);
    cudaGetSymbolAddress((void**)&esrc,   g_esrc);
    cudaGetSymbolAddress((void**)&cdeg,   g_cdeg);
    cudaGetSymbolAddress((void**)&cptr,   g_cptr);
    cudaGetSymbolAddress((void**)&ccur,   g_ccur);
    cudaGetSymbolAddress((void**)&cnodes, g_cnodes);
    cudaGetSymbolAddress((void**)&bsumsN, g_bsumsN);
    cudaGetSymbolAddress((void**)&bsumsC, g_bsumsC);

    // smem (R8 layout: W1 + A + W2 all resident)
    const int SM64  = 2 * (64*72  + 128*72 + 64*72 ) * 2;   //  73728
    const int SM128 = 2 * (64*136 + 128*72 + 128*72) * 2;   // 108544
    const int SM256 = 2 * (64*264 + 128*72 + 256*72) * 2;   // 178176
    cudaFuncSetAttribute((const void*)fused_mlp<64, 128>,  cudaFuncAttributeMaxDynamicSharedMemorySize, SM64);
    cudaFuncSetAttribute((const void*)fused_mlp<128, 256>, cudaFuncAttributeMaxDynamicSharedMemorySize, SM128);
    cudaFuncSetAttribute((const void*)fused_mlp<256, 256>, cudaFuncAttributeMaxDynamicSharedMemorySize, SM256);

    const int GRID = (N + 127) / 128;
    const int nbN = (N + 511) / 512;
    const int nbC = (NC + 511) / 512;

    // ---- init: zero counters + weight conversion (1 launch) ----
    {
        WConv a;
        int off = 0;
        const int CINs[3] = {64, 128, 256};
        for (int i = 0; i < 3; i++) {
            int c = CINs[i];
            a.in[2*i]   = (const float*)d_in[3 + 6*i];       // W1 [c][64] -> [64][c]
            a.hi[2*i]   = w1h[i]; a.lo[2*i] = w1l[i];
            a.K[2*i]    = c;  a.M[2*i] = 64;
            a.off[2*i]  = off; off += c * 64;
            a.in[2*i+1] = (const float*)d_in[3 + 6*i + 4];   // W2 [64][c] -> [c][64]
            a.hi[2*i+1] = w2h[i]; a.lo[2*i+1] = w2l[i];
            a.K[2*i+1]  = 64; a.M[2*i+1] = c;
            a.off[2*i+1] = off; off += 64 * c;
        }
        a.off[6] = off;
        int span = N > off ? N : off;
        init_misc<<<(span + 255) / 256, 256>>>(a, deg, cursor, cdeg, ccur, colsq, N, NC);
    }

    // ---- CSR build (4 launches) ----
    hist_fused<<<(E + N + 255) / 256, 256>>>(ei, E, cluster, N, deg, cdeg);
    scan_block2<<<nbN + nbC, 512>>>(deg, rowptr, bsumsN, N, nbN, cdeg, cptr, bsumsC, NC);
    scan_add_fused<<<nbN + nbC, 512>>>(rowptr, bsumsN, N, nbN, cptr, bsumsC, NC);
    scatter_fused<<<(E + N + 255) / 256, 256>>>(ei, E, cluster, N, rowptr, cursor, esrc,
                                                cptr, ccur, cnodes);

    // ---- layers ----
    fused_mlp<64, 128><<<GRID, 256, SM64>>>(
        x, w1h[0], w1l[0], (const float*)d_in[4], (const float*)d_in[5],
        (const float*)d_in[6], w2h[0], w2l[0], (const float*)d_in[8], y0, N);
    agg_f<64><<<(N + 7) / 8, 256>>>(y0, rowptr, deg, esrc, N);

    fused_mlp<128, 256><<<GRID, 256, SM128>>>(
        y0, w1h[1], w1l[1], (const float*)d_in[10], (const float*)d_in[11],
        (const float*)d_in[12], w2h[1], w2l[1], (const float*)d_in[14], y1, N);
    agg_f<128><<<(N + 7) / 8, 256>>>(y1, rowptr, deg, esrc, N);

    fused_mlp<256, 256><<<GRID, 256, SM256>>>(
        y1, w1h[2], w1l[2], (const float*)d_in[16], (const float*)d_in[17],
        (const float*)d_in[18], w2h[2], w2l[2], (const float*)d_in[20], y2, N);

    // ---- fused layer-2 agg + cluster max-pool + column L2 normalize ----
    pool_agg<<<NC, 128>>>(y2, cptr, cdeg, cnodes, rowptr, deg, esrc, out);
    colsq_kernel<<<(NC + 49) / 50, 512>>>(out, colsq, NC);
    scale_kernel<<<(NC * 128 + 255) / 256, 256>>>(out, colsq, NC);
}

// round 12
// speedup vs baseline: 1.4985x; 1.1480x over previous
#include <cuda_runtime.h>
#include <cuda_bf16.h>
#include <cstdint>

#define LN_EPS 1e-5f

// ---------------- scratch (device globals: allocation-free) ----------------
__device__ __align__(128) float g_y0[100000 * 128];
__device__ __align__(128) float g_y1[100000 * 256];
__device__ __align__(128) float g_y2[100000 * 256];   // layer2 GEMM out only
__device__ __align__(128) __nv_bfloat16 g_w1thi0[64*64],  g_w1tlo0[64*64];
__device__ __align__(128) __nv_bfloat16 g_w1thi1[64*128], g_w1tlo1[64*128];
__device__ __align__(128) __nv_bfloat16 g_w1thi2[64*256], g_w1tlo2[64*256];
__device__ __align__(128) __nv_bfloat16 g_w2thi0[64*64],  g_w2tlo0[64*64];
__device__ __align__(128) __nv_bfloat16 g_w2thi1[128*64], g_w2tlo1[128*64];
__device__ __align__(128) __nv_bfloat16 g_w2thi2[256*64], g_w2tlo2[256*64];
__device__ float g_colsq[512];

// CSR scratch
__device__ int g_deg[100000];
__device__ int g_rowptr[100000];
__device__ int g_cursor[100000];
__device__ int g_esrc[800000];
__device__ int g_cdeg[10000];
__device__ int g_cptr[10000];
__device__ int g_ccur[10000];
__device__ int g_cnodes[100000];
__device__ int g_bsumsN[512];
__device__ int g_bsumsC[512];

__device__ __forceinline__ float neg_inf() { return __int_as_float(0xff800000); }

__device__ __forceinline__ void split2(float a, float b, uint32_t& hi, uint32_t& lo) {
    __nv_bfloat16 ah = __float2bfloat16_rn(a);
    __nv_bfloat16 bh = __float2bfloat16_rn(b);
    __nv_bfloat16 al = __float2bfloat16_rn(a - __bfloat162float(ah));
    __nv_bfloat16 bl = __float2bfloat16_rn(b - __bfloat162float(bh));
    __nv_bfloat162 h = __halves2bfloat162(ah, bh);
    __nv_bfloat162 l = __halves2bfloat162(al, bl);
    hi = *reinterpret_cast<uint32_t*>(&h);
    lo = *reinterpret_cast<uint32_t*>(&l);
}

__device__ __forceinline__ void mma16816(float* c, const uint32_t* a,
                                         uint32_t b0, uint32_t b1) {
    asm volatile(
        "mma.sync.aligned.m16n8k16.row.col.f32.bf16.bf16.f32 "
        "{%0,%1,%2,%3}, {%4,%5,%6,%7}, {%8,%9}, {%0,%1,%2,%3};"
        : "+f"(c[0]), "+f"(c[1]), "+f"(c[2]), "+f"(c[3])
        : "r"(a[0]), "r"(a[1]), "r"(a[2]), "r"(a[3]), "r"(b0), "r"(b1));
}

__device__ __forceinline__ uint32_t sm_off(const void* p) {
    uint32_t a;
    asm("{ .reg .u64 t; cvta.to.shared.u64 t, %1; cvt.u32.u64 %0, t; }" : "=r"(a) : "l"(p));
    return a;
}

__device__ __forceinline__ void ldsm_x4(uint32_t& r0, uint32_t& r1,
                                        uint32_t& r2, uint32_t& r3, uint32_t addr) {
    asm volatile("ldmatrix.sync.aligned.m8n8.x4.shared.b16 {%0,%1,%2,%3}, [%4];"
                 : "=r"(r0), "=r"(r1), "=r"(r2), "=r"(r3) : "r"(addr));
}

// ---------------- init: zero CSR counters + convert all weights -------------
struct WConv {
    const float* in[6];
    __nv_bfloat16* hi[6];
    __nv_bfloat16* lo[6];
    int K[6], M[6];
    int off[7];
};

__global__ void init_misc(WConv a, int* __restrict__ deg, int* __restrict__ cursor,
                          int* __restrict__ cdeg, int* __restrict__ ccur,
                          float* __restrict__ colsq, int n, int nc)
{
    int gid = blockIdx.x * blockDim.x + threadIdx.x;
    if (gid < n) { deg[gid] = 0; cursor[gid] = 0; }
    if (gid < nc) { cdeg[gid] = 0; ccur[gid] = 0; }
    if (gid < 512) colsq[gid] = 0.f;
    if (gid < a.off[6]) {
        int s = 0;
#pragma unroll
        for (int i = 1; i < 6; i++) if (gid >= a.off[i]) s = i;
        int local = gid - a.off[s];
        int M = a.M[s], K = a.K[s];
        int k = local / M, m = local - k * M;
        float v = __ldg(a.in[s] + local);
        __nv_bfloat16 h = __float2bfloat16_rn(v);
        a.hi[s][m * K + k] = h;
        a.lo[s][m * K + k] = __float2bfloat16_rn(v - __bfloat162float(h));
    }
}

// ---------------- CSR build --------------------------------------------------
__global__ void hist_fused(const int* __restrict__ ei, int E,
                           const int* __restrict__ cluster, int n,
                           int* __restrict__ deg, int* __restrict__ cdeg)
{
    int gid = blockIdx.x * blockDim.x + threadIdx.x;
    if (gid < E) {
        atomicAdd(&deg[__ldg(ei + E + gid)], 1);
    } else if (gid < E + n) {
        atomicAdd(&cdeg[__ldg(cluster + gid - E)], 1);
    }
}

__global__ __launch_bounds__(512) void scan_block2(
    const int* __restrict__ inN, int* __restrict__ outN, int* __restrict__ sumsN, int n, int nbN,
    const int* __restrict__ inC, int* __restrict__ outC, int* __restrict__ sumsC, int nc)
{
    __shared__ int s[512];
    int tid = threadIdx.x;
    const int* in;  int* out; int* sums; int len; int blk;
    if ((int)blockIdx.x < nbN) { in = inN; out = outN; sums = sumsN; len = n;  blk = blockIdx.x; }
    else                       { in = inC; out = outC; sums = sumsC; len = nc; blk = blockIdx.x - nbN; }
    int i = blk * 512 + tid;
    int v = (i < len) ? in[i] : 0;
    s[tid] = v;
    __syncthreads();
#pragma unroll
    for (int off = 1; off < 512; off <<= 1) {
        int t = (tid >= off) ? s[tid - off] : 0;
        __syncthreads();
        s[tid] += t;
        __syncthreads();
    }
    if (i < len) out[i] = s[tid] - v;
    if (tid == 511) sums[blk] = s[511];
}

__global__ __launch_bounds__(512) void scan_add_fused(
    int* __restrict__ outN, const int* __restrict__ sumsN, int n, int nbN,
    int* __restrict__ outC, const int* __restrict__ sumsC, int nc)
{
    __shared__ int red[16];
    __shared__ int total;
    int tid = threadIdx.x;
    int* out; const int* sums; int len; int blk;
    if ((int)blockIdx.x < nbN) { out = outN; sums = sumsN; len = n;  blk = blockIdx.x; }
    else                       { out = outC; sums = sumsC; len = nc; blk = blockIdx.x - nbN; }
    int p = 0;
    for (int i = tid; i < blk; i += 512) p += sums[i];
#pragma unroll
    for (int off = 16; off >= 1; off >>= 1) p += __shfl_xor_sync(0xffffffffu, p, off);
    if ((tid & 31) == 0) red[tid >> 5] = p;
    __syncthreads();
    if (tid == 0) {
        int t = 0;
#pragma unroll
        for (int i = 0; i < 16; i++) t += red[i];
        total = t;
    }
    __syncthreads();
    int i = blk * 512 + tid;
    if (i < len) out[i] += total;
}

__global__ void scatter_fused(const int* __restrict__ ei, int E,
                              const int* __restrict__ cluster, int n,
                              const int* __restrict__ rowptr, int* __restrict__ cursor,
                              int* __restrict__ esrc,
                              const int* __restrict__ cptr, int* __restrict__ ccur,
                              int* __restrict__ cnodes)
{
    int gid = blockIdx.x * blockDim.x + threadIdx.x;
    if (gid < E) {
        int src = __ldg(ei + gid);
        int tgt = __ldg(ei + E + gid);
        int pos = rowptr[tgt] + atomicAdd(&cursor[tgt], 1);
        esrc[pos] = src;
    } else if (gid < E + n) {
        int i = gid - E;
        int cl = __ldg(cluster + i);
        int pos = cptr[cl] + atomicAdd(&ccur[cl], 1);
        cnodes[pos] = i;
    }
}

// ---------------- fused MLP layer: gemm1+bias+LN+ReLU+gemm2+bias ------------
// Ain [n, C] fp32; W1T [64][C] split bf16, W2T [C][64] split bf16
// Y row stride OS floats; first C cols written here
// A-staging software-pipelined: chunk kc+1 prefetched to regs during MMA of kc
template<int C, int OS>
__global__ __launch_bounds__(256) void fused_mlp(
    const float* __restrict__ Ain,
    const __nv_bfloat16* __restrict__ W1hi, const __nv_bfloat16* __restrict__ W1lo,
    const float* __restrict__ b1, const float* __restrict__ gam,
    const float* __restrict__ bet,
    const __nv_bfloat16* __restrict__ W2hi, const __nv_bfloat16* __restrict__ W2lo,
    const float* __restrict__ b2,
    float* __restrict__ Y, int n)
{
    constexpr int AS  = 72;
    constexpr int WS  = C + 8;
    constexpr int NKC = C / 64;
    constexpr int NG  = C / 64;
    constexpr int W1E = 64 * WS;
    constexpr int AE  = 128 * AS;
    extern __shared__ __align__(16) __nv_bfloat16 sm[];
    __nv_bfloat16* W1s0 = sm;
    __nv_bfloat16* W1s1 = sm + W1E;
    __nv_bfloat16* As0  = sm + 2 * W1E;
    __nv_bfloat16* As1  = As0 + AE;
    __nv_bfloat16* W2s0 = As1 + AE;
    __nv_bfloat16* W2s1 = W2s0 + C * AS;

    const int tid = threadIdx.x, wid = tid >> 5, lane = tid & 31;
    const int g = lane >> 2, q = lane & 3;
    const int r0b = blockIdx.x * 128;

    // load weights (W1 + W2 up front)
    {
        constexpr int VPR = C / 8;
        for (int i = tid; i < 64 * VPR; i += 256) {
            int m = i / VPR, seg = i - m * VPR;
            *(uint4*)&W1s0[m * WS + seg * 8] = __ldg((const uint4*)(W1hi + (size_t)m * C) + seg);
            *(uint4*)&W1s1[m * WS + seg * 8] = __ldg((const uint4*)(W1lo + (size_t)m * C) + seg);
        }
        for (int i = tid; i < C * 8; i += 256) {
            int m = i >> 3, seg = i & 7;
            *(uint4*)&W2s0[m * AS + seg * 8] = __ldg((const uint4*)(W2hi + (size_t)m * 64) + seg);
            *(uint4*)&W2s1[m * AS + seg * 8] = __ldg((const uint4*)(W2lo + (size_t)m * 64) + seg);
        }
    }

    // per-thread ldmatrix address bases
    const int arow = wid * 16 + (lane & 15);
    const int acol = ((lane >> 4) & 1) * 8;
    const uint32_t a_hi = sm_off(As0 + arow * AS + acol);
    const uint32_t a_lo = sm_off(As1 + arow * AS + acol);
    const int brow = (lane & 7) + ((lane >> 4) << 3);
    const int bk8  = ((lane >> 3) & 1) * 8;
    const uint32_t w1h_b = sm_off(W1s0 + brow * WS + bk8);
    const uint32_t w1l_b = sm_off(W1s1 + brow * WS + bk8);
    const uint32_t w2h_b = sm_off(W2s0 + brow * AS + bk8);
    const uint32_t w2l_b = sm_off(W2s1 + brow * AS + bk8);

    // staging map: per thread 16 entries, entry r -> i = tid + r*256
    const int sm_m = tid >> 5;            // row for r=0; rows step by 8 per r
    const int sm_e = tid & 31;            // float2 index within 64-col chunk

    float acc[8][4] = {};

    // stage chunk 0
    {
#pragma unroll
        for (int rpt = 0; rpt < 16; rpt++) {
            int m = sm_m + rpt * 8;
            int r = r0b + m;
            uint32_t h = 0, l = 0;
            if (r < n) {
                float2 v = __ldg((const float2*)Ain + (size_t)r * (C / 2) + sm_e);
                split2(v.x, v.y, h, l);
            }
            *(uint32_t*)&As0[m * AS + 2 * sm_e] = h;
            *(uint32_t*)&As1[m * AS + 2 * sm_e] = l;
        }
    }
    __syncthreads();

    for (int kc = 0; kc < NKC; kc++) {
        // prefetch next chunk to registers (overlaps with MMA below)
        float2 pf[16];
        if (kc + 1 < NKC) {
#pragma unroll
            for (int rpt = 0; rpt < 16; rpt++) {
                int m = sm_m + rpt * 8;
                int r = r0b + m;
                pf[rpt] = (r < n)
                    ? __ldg((const float2*)Ain + (size_t)r * (C / 2) + (kc + 1) * 32 + sm_e)
                    : make_float2(0.f, 0.f);
            }
        }

#pragma unroll
        for (int ks = 0; ks < 4; ks++) {
            const int k0 = ks * 16;
            uint32_t ah[4], al[4];
            ldsm_x4(ah[0], ah[1], ah[2], ah[3], a_hi + k0 * 2);
            ldsm_x4(al[0], al[1], al[2], al[3], a_lo + k0 * 2);
            const int kg = kc * 64 + k0;
#pragma unroll
            for (int jj = 0; jj < 8; jj += 2) {
                uint32_t p0, p1, p2, p3, l0, l1, l2, l3;
                ldsm_x4(p0, p1, p2, p3, w1h_b + (8 * jj * WS + kg) * 2);
                ldsm_x4(l0, l1, l2, l3, w1l_b + (8 * jj * WS + kg) * 2);
                mma16816(acc[jj],     ah, p0, p1);
                mma16816(acc[jj],     ah, l0, l1);
                mma16816(acc[jj],     al, p0, p1);
                mma16816(acc[jj + 1], ah, p2, p3);
                mma16816(acc[jj + 1], ah, l2, l3);
                mma16816(acc[jj + 1], al, p2, p3);
            }
        }

        if (kc + 1 < NKC) {
            __syncthreads();     // all MMA reads of As done
#pragma unroll
            for (int rpt = 0; rpt < 16; rpt++) {
                int m = sm_m + rpt * 8;
                uint32_t h, l;
                split2(pf[rpt].x, pf[rpt].y, h, l);
                *(uint32_t*)&As0[m * AS + 2 * sm_e] = h;
                *(uint32_t*)&As1[m * AS + 2 * sm_e] = l;
            }
            __syncthreads();
        }
    }

    // ---- gemm1 epilogue: bias + LN (quad shuffle) + ReLU -> H in As --------
    {
        float v0[16], v1[16];
        float s0 = 0.f, q0 = 0.f, s1 = 0.f, q1 = 0.f;
#pragma unroll
        for (int j = 0; j < 8; j++) {
            int c0 = 8*j + 2*q;
            float bx = __ldg(b1 + c0), by = __ldg(b1 + c0 + 1);
            float a = acc[j][0] + bx, b = acc[j][1] + by;
            float c = acc[j][2] + bx, d = acc[j][3] + by;
            v0[2*j] = a; v0[2*j+1] = b; v1[2*j] = c; v1[2*j+1] = d;
            s0 += a + b; q0 += a*a + b*b;
            s1 += c + d; q1 += c*c + d*d;
        }
#pragma unroll
        for (int off = 1; off < 4; off <<= 1) {
            s0 += __shfl_xor_sync(0xffffffffu, s0, off);
            q0 += __shfl_xor_sync(0xffffffffu, q0, off);
            s1 += __shfl_xor_sync(0xffffffffu, s1, off);
            q1 += __shfl_xor_sync(0xffffffffu, q1, off);
        }
        float mu0 = s0 * (1.f/64.f), var0 = q0 * (1.f/64.f) - mu0*mu0;
        float mu1 = s1 * (1.f/64.f), var1 = q1 * (1.f/64.f) - mu1*mu1;
        float rs0 = rsqrtf(var0 + LN_EPS), rs1 = rsqrtf(var1 + LN_EPS);
        __syncthreads();
        int rl0 = wid * 16 + g, rl1 = rl0 + 8;
#pragma unroll
        for (int j = 0; j < 8; j++) {
            int c0 = 8*j + 2*q;
            float ga = __ldg(gam + c0), gb = __ldg(gam + c0 + 1);
            float ba = __ldg(bet + c0), bb = __ldg(bet + c0 + 1);
            float f0 = fmaxf((v0[2*j]   - mu0) * rs0 * ga + ba, 0.f);
            float f1 = fmaxf((v0[2*j+1] - mu0) * rs0 * gb + bb, 0.f);
            float f2 = fmaxf((v1[2*j]   - mu1) * rs1 * ga + ba, 0.f);
            float f3 = fmaxf((v1[2*j+1] - mu1) * rs1 * gb + bb, 0.f);
            uint32_t h, l;
            split2(f0, f1, h, l);
            *(uint32_t*)&As0[rl0 * AS + c0] = h;
            *(uint32_t*)&As1[rl0 * AS + c0] = l;
            split2(f2, f3, h, l);
            *(uint32_t*)&As0[rl1 * AS + c0] = h;
            *(uint32_t*)&As1[rl1 * AS + c0] = l;
        }
    }
    __syncthreads();

    // ---- gemm2: H[128,64] @ W2 -> Y[:, 0:C] --------------------------------
    const int rg0 = r0b + wid * 16 + g;
    const int rg1 = rg0 + 8;

#pragma unroll
    for (int ng = 0; ng < NG; ng++) {
        float acc2[8][4] = {};
#pragma unroll
        for (int ks = 0; ks < 4; ks++) {
            const int k0 = ks * 16;
            uint32_t ah[4], al[4];
            ldsm_x4(ah[0], ah[1], ah[2], ah[3], a_hi + k0 * 2);
            ldsm_x4(al[0], al[1], al[2], al[3], a_lo + k0 * 2);
#pragma unroll
            for (int jj = 0; jj < 8; jj += 2) {
                uint32_t p0, p1, p2, p3, l0, l1, l2, l3;
                ldsm_x4(p0, p1, p2, p3, w2h_b + ((ng * 64 + 8 * jj) * AS + k0) * 2);
                ldsm_x4(l0, l1, l2, l3, w2l_b + ((ng * 64 + 8 * jj) * AS + k0) * 2);
                mma16816(acc2[jj],     ah, p0, p1);
                mma16816(acc2[jj],     ah, l0, l1);
                mma16816(acc2[jj],     al, p0, p1);
                mma16816(acc2[jj + 1], ah, p2, p3);
                mma16816(acc2[jj + 1], ah, l2, l3);
                mma16816(acc2[jj + 1], al, p2, p3);
            }
        }
        if (rg0 < n) {
            float2* orow = (float2*)(Y + (size_t)rg0 * OS) + ng * 32;
#pragma unroll
            for (int j = 0; j < 8; j++) {
                int c0 = 8*j + 2*q;
                orow[4*j + q] = make_float2(acc2[j][0] + __ldg(b2 + ng*64 + c0),
                                            acc2[j][1] + __ldg(b2 + ng*64 + c0 + 1));
            }
        }
        if (rg1 < n) {
            float2* orow = (float2*)(Y + (size_t)rg1 * OS) + ng * 32;
#pragma unroll
            for (int j = 0; j < 8; j++) {
                int c0 = 8*j + 2*q;
                orow[4*j + q] = make_float2(acc2[j][2] + __ldg(b2 + ng*64 + c0),
                                            acc2[j][3] + __ldg(b2 + ng*64 + c0 + 1));
            }
        }
    }
}

// ---------------- CSR gather-max aggregation (fp32, unrolled x4) ------------
template<int C>
__global__ __launch_bounds__(256) void agg_f(
    float* __restrict__ Y, const int* __restrict__ rowptr,
    const int* __restrict__ deg, const int* __restrict__ esrc, int n)
{
    int w = (blockIdx.x * blockDim.x + threadIdx.x) >> 5;
    if (w >= n) return;
    const int lane = threadIdx.x & 31;
    constexpr int EPL = C / 64;
    float2 mx[EPL];
#pragma unroll
    for (int i = 0; i < EPL; i++) mx[i] = make_float2(neg_inf(), neg_inf());
    int d = __ldg(deg + w), base = __ldg(rowptr + w);
    int j = 0;
    for (; j + 3 < d; j += 4) {
        int s0 = __ldg(esrc + base + j);
        int s1 = __ldg(esrc + base + j + 1);
        int s2 = __ldg(esrc + base + j + 2);
        int s3 = __ldg(esrc + base + j + 3);
        const float2* r0 = (const float2*)(Y + (size_t)s0 * (2 * C));
        const float2* r1 = (const float2*)(Y + (size_t)s1 * (2 * C));
        const float2* r2 = (const float2*)(Y + (size_t)s2 * (2 * C));
        const float2* r3 = (const float2*)(Y + (size_t)s3 * (2 * C));
#pragma unroll
        for (int i = 0; i < EPL; i++) {
            float2 v0 = __ldg(r0 + lane + i * 32);
            float2 v1 = __ldg(r1 + lane + i * 32);
            float2 v2 = __ldg(r2 + lane + i * 32);
            float2 v3 = __ldg(r3 + lane + i * 32);
            float ax = fmaxf(fmaxf(v0.x, v1.x), fmaxf(v2.x, v3.x));
            float ay = fmaxf(fmaxf(v0.y, v1.y), fmaxf(v2.y, v3.y));
            mx[i].x = fmaxf(mx[i].x, ax);
            mx[i].y = fmaxf(mx[i].y, ay);
        }
    }
    for (; j < d; j++) {
        int s0 = __ldg(esrc + base + j);
        const float2* r0 = (const float2*)(Y + (size_t)s0 * (2 * C));
#pragma unroll
        for (int i = 0; i < EPL; i++) {
            float2 v0 = __ldg(r0 + lane + i * 32);
            mx[i].x = fmaxf(mx[i].x, v0.x);
            mx[i].y = fmaxf(mx[i].y, v0.y);
        }
    }
    float2* orow = (float2*)(Y + (size_t)w * (2 * C) + C);
#pragma unroll
    for (int i = 0; i < EPL; i++)
        orow[lane + i * 32] = d ? mx[i] : make_float2(0.f, 0.f);
}

// ---------------- fused layer-2 agg + cluster max-pool ----------------------
__global__ __launch_bounds__(128) void pool_agg(
    const float* __restrict__ Y,
    const int* __restrict__ cptr, const int* __restrict__ cdeg,
    const int* __restrict__ cnodes,
    const int* __restrict__ rowptr, const int* __restrict__ deg,
    const int* __restrict__ esrc,
    float* __restrict__ out)
{
    int cl = blockIdx.x, t = threadIdx.x;
    int cd = __ldg(cdeg + cl), cbase = __ldg(cptr + cl);
    float2 m0 = make_float2(neg_inf(), neg_inf());
    float2 m1 = m0;
    bool zerodeg = false;
    for (int j = 0; j < cd; j++) {
        int nd = __ldg(cnodes + cbase + j);
        const float2* row = (const float2*)(Y + (size_t)nd * 256);
        float2 v = __ldg(row + t);
        m0.x = fmaxf(m0.x, v.x); m0.y = fmaxf(m0.y, v.y);
        int d = __ldg(deg + nd), eb = __ldg(rowptr + nd);
        if (d == 0) zerodeg = true;
        int e = 0;
        for (; e + 1 < d; e += 2) {
            int s0 = __ldg(esrc + eb + e);
            int s1 = __ldg(esrc + eb + e + 1);
            float2 w0 = __ldg((const float2*)(Y + (size_t)s0 * 256) + t);
            float2 w1 = __ldg((const float2*)(Y + (size_t)s1 * 256) + t);
            m1.x = fmaxf(m1.x, fmaxf(w0.x, w1.x));
            m1.y = fmaxf(m1.y, fmaxf(w0.y, w1.y));
        }
        if (e < d) {
            int s0 = __ldg(esrc + eb + e);
            float2 w0 = __ldg((const float2*)(Y + (size_t)s0 * 256) + t);
            m1.x = fmaxf(m1.x, w0.x);
            m1.y = fmaxf(m1.y, w0.y);
        }
    }
    if (cd == 0) {
        m0 = make_float2(0.f, 0.f);
        m1 = m0;
    } else if (zerodeg) {
        m1.x = fmaxf(m1.x, 0.f);
        m1.y = fmaxf(m1.y, 0.f);
    }
    float2* orow = (float2*)(out + (size_t)cl * 512);
    orow[t] = m0;
    orow[t + 128] = m1;
}

// ---------------- column L2 normalize ---------------------------------------
__global__ __launch_bounds__(512) void colsq_kernel(const float* __restrict__ out,
                                                    float* __restrict__ colsq, int nc)
{
    const int ROWS = 50;
    int c  = threadIdx.x;
    int r0 = blockIdx.x * ROWS;
    int r1 = min(r0 + ROWS, nc);
    float s = 0.f;
    for (int r = r0; r < r1; r++) {
        float f = out[(size_t)r * 512 + c];
        s += f * f;
    }
    atomicAdd(colsq + c, s);
}

__global__ void scale_kernel(float* __restrict__ out, const float* __restrict__ colsq, int nc)
{
    int gid = blockIdx.x * blockDim.x + threadIdx.x;
    if (gid >= nc * 128) return;
    int c4 = gid & 127;
    float4 v = *(float4*)(out + (size_t)gid * 4);
    float4 s = *(const float4*)(colsq + c4 * 4);
    v.x *= rsqrtf(s.x); v.y *= rsqrtf(s.y);
    v.z *= rsqrtf(s.z); v.w *= rsqrtf(s.w);
    *(float4*)(out + (size_t)gid * 4) = v;
}

// ---------------- launch ----------------------------------------------------
extern "C" void kernel_launch(void* const* d_in, const int* in_sizes, int n_in,
                              void* d_out, int out_size)
{
    const float* x       = (const float*)d_in[0];
    const int*   ei      = (const int*)d_in[1];
    const int*   cluster = (const int*)d_in[2];
    const int N  = in_sizes[0] / 64;
    const int E  = in_sizes[1] / 2;
    const int NC = out_size / 512;
    float* out = (float*)d_out;

    float *y0, *y1, *y2, *colsq;
    __nv_bfloat16 *w1h[3], *w1l[3], *w2h[3], *w2l[3];
    int *deg, *rowptr, *cursor, *esrc, *cdeg, *cptr, *ccur, *cnodes, *bsumsN, *bsumsC;
    cudaGetSymbolAddress((void**)&y0, g_y0);
    cudaGetSymbolAddress((void**)&y1, g_y1);
    cudaGetSymbolAddress((void**)&y2, g_y2);
    cudaGetSymbolAddress((void**)&w1h[0], g_w1thi0); cudaGetSymbolAddress((void**)&w1l[0], g_w1tlo0);
    cudaGetSymbolAddress((void**)&w1h[1], g_w1thi1); cudaGetSymbolAddress((void**)&w1l[1], g_w1tlo1);
    cudaGetSymbolAddress((void**)&w1h[2], g_w1thi2); cudaGetSymbolAddress((void**)&w1l[2], g_w1tlo2);
    cudaGetSymbolAddress((void**)&w2h[0], g_w2thi0); cudaGetSymbolAddress((void**)&w2l[0], g_w2tlo0);
    cudaGetSymbolAddress((void**)&w2h[1], g_w2thi1); cudaGetSymbolAddress((void**)&w2l[1], g_w2tlo1);
    cudaGetSymbolAddress((void**)&w2h[2], g_w2thi2); cudaGetSymbolAddress((void**)&w2l[2], g_w2tlo2);
    cudaGetSymbolAddress((void**)&colsq,  g_colsq);
    cudaGetSymbolAddress((void**)&deg,    g_deg);
    cudaGetSymbolAddress((void**)&rowptr, g_rowptr);
    cudaGetSymbolAddress((void**)&cursor, g_cursor);
    cudaGetSymbolAddress((void**)&esrc,   g_esrc);
    cudaGetSymbolAddress((void**)&cdeg,   g_cdeg);
    cudaGetSymbolAddress((void**)&cptr,   g_cptr);
    cudaGetSymbolAddress((void**)&ccur,   g_ccur);
    cudaGetSymbolAddress((void**)&cnodes, g_cnodes);
    cudaGetSymbolAddress((void**)&bsumsN, g_bsumsN);
    cudaGetSymbolAddress((void**)&bsumsC, g_bsumsC);

    const int SM64  = 2 * (64*72  + 128*72 + 64*72 ) * 2;   //  73728
    const int SM128 = 2 * (64*136 + 128*72 + 128*72) * 2;   // 108544
    const int SM256 = 2 * (64*264 + 128*72 + 256*72) * 2;   // 178176
    cudaFuncSetAttribute((const void*)fused_mlp<64, 128>,  cudaFuncAttributeMaxDynamicSharedMemorySize, SM64);
    cudaFuncSetAttribute((const void*)fused_mlp<128, 256>, cudaFuncAttributeMaxDynamicSharedMemorySize, SM128);
    cudaFuncSetAttribute((const void*)fused_mlp<256, 256>, cudaFuncAttributeMaxDynamicSharedMemorySize, SM256);

    const int GRID = (N + 127) / 128;
    const int nbN = (N + 511) / 512;
    const int nbC = (NC + 511) / 512;

    // ---- init: zero counters + weight conversion (1 launch) ----
    {
        WConv a;
        int off = 0;
        const int CINs[3] = {64, 128, 256};
        for (int i = 0; i < 3; i++) {
            int c = CINs[i];
            a.in[2*i]   = (const float*)d_in[3 + 6*i];
            a.hi[2*i]   = w1h[i]; a.lo[2*i] = w1l[i];
            a.K[2*i]    = c;  a.M[2*i] = 64;
            a.off[2*i]  = off; off += c * 64;
            a.in[2*i+1] = (const float*)d_in[3 + 6*i + 4];
            a.hi[2*i+1] = w2h[i]; a.lo[2*i+1] = w2l[i];
            a.K[2*i+1]  = 64; a.M[2*i+1] = c;
            a.off[2*i+1] = off; off += 64 * c;
        }
        a.off[6] = off;
        int span = N > off ? N : off;
        init_misc<<<(span + 255) / 256, 256>>>(a, deg, cursor, cdeg, ccur, colsq, N, NC);
    }

    // ---- CSR build (4 launches) ----
    hist_fused<<<(E + N + 255) / 256, 256>>>(ei, E, cluster, N, deg, cdeg);
    scan_block2<<<nbN + nbC, 512>>>(deg, rowptr, bsumsN, N, nbN, cdeg, cptr, bsumsC, NC);
    scan_add_fused<<<nbN + nbC, 512>>>(rowptr, bsumsN, N, nbN, cptr, bsumsC, NC);
    scatter_fused<<<(E + N + 255) / 256, 256>>>(ei, E, cluster, N, rowptr, cursor, esrc,
                                                cptr, ccur, cnodes);

    // ---- layers ----
    fused_mlp<64, 128><<<GRID, 256, SM64>>>(
        x, w1h[0], w1l[0], (const float*)d_in[4], (const float*)d_in[5],
        (const float*)d_in[6], w2h[0], w2l[0], (const float*)d_in[8], y0, N);
    agg_f<64><<<(N + 7) / 8, 256>>>(y0, rowptr, deg, esrc, N);

    fused_mlp<128, 256><<<GRID, 256, SM128>>>(
        y0, w1h[1], w1l[1], (const float*)d_in[10], (const float*)d_in[11],
        (const float*)d_in[12], w2h[1], w2l[1], (const float*)d_in[14], y1, N);
    agg_f<128><<<(N + 7) / 8, 256>>>(y1, rowptr, deg, esrc, N);

    fused_mlp<256, 256><<<GRID, 256, SM256>>>(
        y1, w1h[2], w1l[2], (const float*)d_in[16], (const float*)d_in[17],
        (const float*)d_in[18], w2h[2], w2l[2], (const float*)d_in[20], y2, N);

    // ---- fused layer-2 agg + cluster max-pool + column L2 normalize ----
    pool_agg<<<NC, 128>>>(y2, cptr, cdeg, cnodes, rowptr, deg, esrc, out);
    colsq_kernel<<<(NC + 49) / 50, 512>>>(out, colsq, NC);
    scale_kernel<<<(NC * 128 + 255) / 256, 256>>>(out, colsq, NC);
}